// round 1
// baseline (speedup 1.0000x reference)
#include <cuda_runtime.h>
#include <math.h>

// ---------------- problem constants ----------------
#define DIMC    96
#define NHC     3
#define HEADC   32
#define WSC     7
#define SHIFTC  3
#define PC      5
#define HC      56
#define NWHC    8
#define NWC     64        // windows per batch
#define TPC     320       // prompt tokens per batch
#define NNC     54        // tokens per window (P + 49)
#define BATCHC  64
#define TOKC    3456      // tokens per batch (H*W + TP)
#define MROWS   (BATCHC * NWC * NNC)   // 221184 == BATCHC*TOKC
#define HIDC    384
#define SCALEC  0.17677669529663687f   // 32^-0.5

// ---------------- scratch (device globals; no cudaMalloc allowed) ----------------
__device__ float g_xw   [MROWS * DIMC];      // LN1'd, window-ordered
__device__ float g_qkv  [(size_t)MROWS * 3 * DIMC];
__device__ float g_attno[MROWS * DIMC];      // attention output, window-ordered
__device__ float g_y    [MROWS * DIMC];      // residual-1 result, token order
__device__ float g_yn   [MROWS * DIMC];      // LN2(y)
__device__ float g_h    [(size_t)MROWS * HIDC];

// map window-layout row (bw in [0,4096), n in [0,54)) -> global token index in x/y
__device__ __forceinline__ int map_token(int bw, int n) {
    int b = bw >> 6;       // / 64
    int w = bw & 63;
    int tok;
    if (n < PC) {
        tok = w * PC + n;
    } else {
        int p  = n - PC;
        int r  = p / 7, c = p % 7;
        int wh = w >> 3, ww = w & 7;
        int hr = wh * 7 + r + SHIFTC; if (hr >= HC) hr -= HC;
        int wc = ww * 7 + c + SHIFTC; if (wc >= HC) wc -= HC;
        tok = TPC + hr * HC + wc;
    }
    return b * TOKC + tok;
}

__device__ __forceinline__ float warp_sum(float v) {
    #pragma unroll
    for (int o = 16; o; o >>= 1) v += __shfl_xor_sync(0xffffffffu, v, o);
    return v;
}

// ---------------- K1: LN1 + shifted-window gather (one warp per row) ----------------
__global__ __launch_bounds__(256)
void ln_gather_kernel(const float* __restrict__ x,
                      const float* __restrict__ g, const float* __restrict__ bta) {
    int row  = (blockIdx.x * blockDim.x + threadIdx.x) >> 5;
    int lane = threadIdx.x & 31;
    if (row >= MROWS) return;
    int bw = row / NNC, n = row % NNC;
    const float* src = x + (size_t)map_token(bw, n) * DIMC;
    float v0 = src[lane], v1 = src[lane + 32], v2 = src[lane + 64];
    float mean = warp_sum(v0 + v1 + v2) * (1.f / 96.f);
    float d0 = v0 - mean, d1 = v1 - mean, d2 = v2 - mean;
    float var = warp_sum(d0 * d0 + d1 * d1 + d2 * d2) * (1.f / 96.f);
    float inv = rsqrtf(var + 1e-5f);
    float* dst = g_xw + (size_t)row * DIMC;
    dst[lane]      = d0 * inv * g[lane]      + bta[lane];
    dst[lane + 32] = d1 * inv * g[lane + 32] + bta[lane + 32];
    dst[lane + 64] = d2 * inv * g[lane + 64] + bta[lane + 64];
}

// ---------------- K4: plain LN (token order) ----------------
__global__ __launch_bounds__(256)
void ln_plain_kernel(const float* __restrict__ y,
                     const float* __restrict__ g, const float* __restrict__ bta,
                     float* __restrict__ out) {
    int row  = (blockIdx.x * blockDim.x + threadIdx.x) >> 5;
    int lane = threadIdx.x & 31;
    if (row >= MROWS) return;
    const float* src = y + (size_t)row * DIMC;
    float v0 = src[lane], v1 = src[lane + 32], v2 = src[lane + 64];
    float mean = warp_sum(v0 + v1 + v2) * (1.f / 96.f);
    float d0 = v0 - mean, d1 = v1 - mean, d2 = v2 - mean;
    float var = warp_sum(d0 * d0 + d1 * d1 + d2 * d2) * (1.f / 96.f);
    float inv = rsqrtf(var + 1e-5f);
    float* dst = out + (size_t)row * DIMC;
    dst[lane]      = d0 * inv * g[lane]      + bta[lane];
    dst[lane + 32] = d1 * inv * g[lane + 32] + bta[lane + 32];
    dst[lane + 64] = d2 * inv * g[lane + 64] + bta[lane + 64];
}

// ---------------- SGEMM: C(MxN) = A(MxK) @ B(KxN) + epilogue ----------------
// BM=64, BN=96, BK=16, 256 threads, 4x6 microtile.
// MODE 0: +bias -> out[row*N+col]                       (QKV)
// MODE 1: +bias, scatter row->token, += res(x) -> y     (proj + residual-1)
// MODE 2: +bias, exact GELU -> out[row*N+col]           (fc1)
// MODE 3: +bias, += res(y) -> out[row*N+col]            (fc2 + residual-2)
#define BM 64
#define BN 96
#define BK 16

template<int MODE>
__global__ __launch_bounds__(256)
void gemm_kernel(const float* __restrict__ A, const float* __restrict__ Bw,
                 const float* __restrict__ bias, const float* __restrict__ res,
                 float* __restrict__ out, int N, int K) {
    __shared__ float As[BK][BM];
    __shared__ float Bs[BK][BN];

    int tid = threadIdx.x;
    int tx = tid & 15;        // N dir (x6)
    int ty = tid >> 4;        // M dir (x4)
    int m0 = blockIdx.y * BM;
    int n0 = blockIdx.x * BN;

    float acc[4][6];
    #pragma unroll
    for (int i = 0; i < 4; i++)
        #pragma unroll
        for (int j = 0; j < 6; j++) acc[i][j] = 0.f;

    int arow = tid >> 2;            // 0..63
    int akk  = (tid & 3) * 4;       // 0,4,8,12

    for (int k0 = 0; k0 < K; k0 += BK) {
        // stage A (64x16), transposed into As[k][m]
        float4 av = *(const float4*)(A + (size_t)(m0 + arow) * K + k0 + akk);
        As[akk + 0][arow] = av.x;
        As[akk + 1][arow] = av.y;
        As[akk + 2][arow] = av.z;
        As[akk + 3][arow] = av.w;
        // stage B (16x96) : 384 float4, 256 threads
        {
            int i = tid;
            int bk = i / 24, bn = (i % 24) * 4;
            *(float4*)&Bs[bk][bn] = *(const float4*)(Bw + (size_t)(k0 + bk) * N + n0 + bn);
            i = tid + 256;
            if (i < 384) {
                bk = i / 24; bn = (i % 24) * 4;
                *(float4*)&Bs[bk][bn] = *(const float4*)(Bw + (size_t)(k0 + bk) * N + n0 + bn);
            }
        }
        __syncthreads();

        #pragma unroll
        for (int k = 0; k < BK; k++) {
            float4 a4 = *(const float4*)&As[k][ty * 4];
            float2 b0 = *(const float2*)&Bs[k][tx * 6];
            float2 b1 = *(const float2*)&Bs[k][tx * 6 + 2];
            float2 b2 = *(const float2*)&Bs[k][tx * 6 + 4];
            float a[4] = {a4.x, a4.y, a4.z, a4.w};
            float b[6] = {b0.x, b0.y, b1.x, b1.y, b2.x, b2.y};
            #pragma unroll
            for (int i = 0; i < 4; i++)
                #pragma unroll
                for (int j = 0; j < 6; j++)
                    acc[i][j] += a[i] * b[j];
        }
        __syncthreads();
    }

    // epilogue
    float bv[6];
    #pragma unroll
    for (int j = 0; j < 6; j++) bv[j] = bias[n0 + tx * 6 + j];

    #pragma unroll
    for (int i = 0; i < 4; i++) {
        int row = m0 + ty * 4 + i;
        size_t orow;
        if (MODE == 1) orow = (size_t)map_token(row / NNC, row % NNC);
        else           orow = (size_t)row;
        float*       op = out + orow * N + n0 + tx * 6;
        const float* rp = (MODE == 1 || MODE == 3) ? (res + orow * N + n0 + tx * 6) : nullptr;
        #pragma unroll
        for (int j = 0; j < 6; j++) {
            float v = acc[i][j] + bv[j];
            if (MODE == 2) v = 0.5f * v * (1.0f + erff(v * 0.70710678118654752f));
            if (MODE == 1 || MODE == 3) v += rp[j];
            op[j] = v;
        }
    }
}

// ---------------- K3: windowed attention (one block per window, 3 heads) ----------------
__global__ __launch_bounds__(192)
void attn_kernel(const float* __restrict__ qkv, const float* __restrict__ rpb,
                 float* __restrict__ attno) {
    __shared__ float ks[NHC][NNC * HEADC];
    __shared__ float vs[NHC][NNC * HEADC];
    __shared__ float btab[169 * NHC];
    __shared__ int   regn[NNC];

    int bw   = blockIdx.x;          // window id in [0, 4096)
    int base = bw * NNC;
    int tid  = threadIdx.x;

    // stage K,V for all 3 heads
    for (int idx = tid; idx < NHC * NNC * HEADC; idx += 192) {
        int h = idx / (NNC * HEADC);
        int r = idx % (NNC * HEADC);
        int m = r >> 5, d = r & 31;
        const float* p = qkv + (size_t)(base + m) * (3 * DIMC);
        ks[h][r] = p[DIMC     + h * HEADC + d];
        vs[h][r] = p[2 * DIMC + h * HEADC + d];
    }
    for (int i = tid; i < 169 * NHC; i += 192) btab[i] = rpb[i];
    // Swin shift-mask region per position (prompt = -1, never masked)
    for (int i = tid; i < NNC; i += 192) {
        if (i < PC) { regn[i] = -1; }
        else {
            int p = i - PC;
            int r = p / 7, c = p % 7;
            int w = bw & 63;
            int gh = (w >> 3) * 7 + r;
            int gw = (w & 7) * 7 + c;
            int rh = gh < 49 ? 0 : (gh < 53 ? 1 : 2);
            int rw = gw < 49 ? 0 : (gw < 53 ? 1 : 2);
            regn[i] = rh * 3 + rw;
        }
    }
    __syncthreads();

    int head = tid / 64;
    int t    = tid % 64;
    if (t >= NNC) return;

    // Q row in registers (scaled)
    const float4* qp = (const float4*)(qkv + (size_t)(base + t) * (3 * DIMC) + head * HEADC);
    float4 q4[8];
    #pragma unroll
    for (int j = 0; j < 8; j++) {
        q4[j] = qp[j];
        q4[j].x *= SCALEC; q4[j].y *= SCALEC; q4[j].z *= SCALEC; q4[j].w *= SCALEC;
    }

    bool feat = (t >= PC);
    int rt = 0, ct = 0, myreg = -1;
    if (feat) { rt = (t - PC) / 7; ct = (t - PC) % 7; myreg = regn[t]; }

    const float* kh = ks[head];
    float s[NNC];
    #pragma unroll
    for (int m = 0; m < NNC; m++) {
        const float4* k4 = (const float4*)(kh + m * HEADC);
        float a = 0.f;
        #pragma unroll
        for (int j = 0; j < 8; j++) {
            float4 kk = k4[j];
            a += q4[j].x * kk.x + q4[j].y * kk.y + q4[j].z * kk.z + q4[j].w * kk.w;
        }
        float badd = 0.f;
        if (feat && m >= PC) {
            const int rm = (m - PC) / 7, cm = (m - PC) % 7;   // compile-time
            int idx = (rt - rm + 6) * 13 + (ct - cm + 6);
            badd = btab[idx * NHC + head];
            if (regn[m] != myreg) badd -= 100.f;
        }
        s[m] = a + badd;
    }

    // softmax over m
    float mx = s[0];
    #pragma unroll
    for (int m = 1; m < NNC; m++) mx = fmaxf(mx, s[m]);
    float sum = 0.f;
    #pragma unroll
    for (int m = 0; m < NNC; m++) { s[m] = __expf(s[m] - mx); sum += s[m]; }
    float inv = 1.0f / sum;

    // P @ V
    float acc[HEADC];
    #pragma unroll
    for (int d = 0; d < HEADC; d++) acc[d] = 0.f;
    const float* vh = vs[head];
    #pragma unroll
    for (int m = 0; m < NNC; m++) {
        float pm = s[m] * inv;
        const float4* v4 = (const float4*)(vh + m * HEADC);
        #pragma unroll
        for (int j = 0; j < 8; j++) {
            float4 vv = v4[j];
            acc[4 * j + 0] += pm * vv.x;
            acc[4 * j + 1] += pm * vv.y;
            acc[4 * j + 2] += pm * vv.z;
            acc[4 * j + 3] += pm * vv.w;
        }
    }

    float4* op = (float4*)(attno + (size_t)(base + t) * DIMC + head * HEADC);
    #pragma unroll
    for (int j = 0; j < 8; j++)
        op[j] = make_float4(acc[4 * j], acc[4 * j + 1], acc[4 * j + 2], acc[4 * j + 3]);
}

// ---------------- launch ----------------
extern "C" void kernel_launch(void* const* d_in, const int* in_sizes, int n_in,
                              void* d_out, int out_size) {
    const float* x       = (const float*)d_in[0];
    const float* norm1_g = (const float*)d_in[1];
    const float* norm1_b = (const float*)d_in[2];
    const float* qkv_w   = (const float*)d_in[3];
    const float* qkv_b   = (const float*)d_in[4];
    const float* rpb     = (const float*)d_in[5];
    const float* proj_w  = (const float*)d_in[6];
    const float* proj_b  = (const float*)d_in[7];
    const float* norm2_g = (const float*)d_in[8];
    const float* norm2_b = (const float*)d_in[9];
    const float* fc1_w   = (const float*)d_in[10];
    const float* fc1_b   = (const float*)d_in[11];
    const float* fc2_w   = (const float*)d_in[12];
    const float* fc2_b   = (const float*)d_in[13];
    float* out = (float*)d_out;

    float *p_xw, *p_qkv, *p_attno, *p_y, *p_yn, *p_h;
    cudaGetSymbolAddress((void**)&p_xw,    g_xw);
    cudaGetSymbolAddress((void**)&p_qkv,   g_qkv);
    cudaGetSymbolAddress((void**)&p_attno, g_attno);
    cudaGetSymbolAddress((void**)&p_y,     g_y);
    cudaGetSymbolAddress((void**)&p_yn,    g_yn);
    cudaGetSymbolAddress((void**)&p_h,     g_h);

    const int lnBlocks = (MROWS * 32 + 255) / 256;   // one warp per row

    // 1. LN1 + window gather
    ln_gather_kernel<<<lnBlocks, 256>>>(x, norm1_g, norm1_b);
    // 2. QKV GEMM  (M=221184, N=288, K=96)
    gemm_kernel<0><<<dim3(3, MROWS / BM), 256>>>(p_xw, qkv_w, qkv_b, nullptr, p_qkv, 288, 96);
    // 3. windowed attention
    attn_kernel<<<BATCHC * NWC, 192>>>(p_qkv, rpb, p_attno);
    // 4. proj GEMM + scatter + residual-1  (N=96, K=96)
    gemm_kernel<1><<<dim3(1, MROWS / BM), 256>>>(p_attno, proj_w, proj_b, x, p_y, 96, 96);
    // 5. LN2
    ln_plain_kernel<<<lnBlocks, 256>>>(p_y, norm2_g, norm2_b, p_yn);
    // 6. fc1 + GELU  (N=384, K=96)
    gemm_kernel<2><<<dim3(4, MROWS / BM), 256>>>(p_yn, fc1_w, fc1_b, nullptr, p_h, 384, 96);
    // 7. fc2 + residual-2 -> d_out  (N=96, K=384)
    gemm_kernel<3><<<dim3(1, MROWS / BM), 256>>>(p_h, fc2_w, fc2_b, p_y, out, 96, 384);
}

// round 2
// speedup vs baseline: 1.1322x; 1.1322x over previous
#include <cuda_runtime.h>
#include <math.h>

// ---------------- problem constants ----------------
#define DIMC    96
#define NHC     3
#define HEADC   32
#define WSC     7
#define SHIFTC  3
#define PC      5
#define HC      56
#define NWC     64        // windows per batch
#define TPC     320       // prompt tokens per batch
#define NNC     54        // tokens per window (P + 49)
#define BATCHC  64
#define TOKC    3456      // tokens per batch (H*W + TP)
#define MROWS   (BATCHC * NWC * NNC)   // 221184
#define HIDC    384
#define SCALEC  0.17677669529663687f   // 32^-0.5

// ---------------- scratch ----------------
__device__ float g_xw   [MROWS * DIMC];
__device__ float g_qkv  [(size_t)MROWS * 3 * DIMC];
__device__ float g_attno[MROWS * DIMC];
__device__ float g_y    [MROWS * DIMC];
__device__ float g_yn   [MROWS * DIMC];
__device__ float g_h    [(size_t)MROWS * HIDC];

__device__ __forceinline__ int map_token(int bw, int n) {
    int b = bw >> 6;
    int w = bw & 63;
    int tok;
    if (n < PC) {
        tok = w * PC + n;
    } else {
        int p  = n - PC;
        int r  = p / 7, c = p % 7;
        int wh = w >> 3, ww = w & 7;
        int hr = wh * 7 + r + SHIFTC; if (hr >= HC) hr -= HC;
        int wc = ww * 7 + c + SHIFTC; if (wc >= HC) wc -= HC;
        tok = TPC + hr * HC + wc;
    }
    return b * TOKC + tok;
}

__device__ __forceinline__ float warp_sum(float v) {
    #pragma unroll
    for (int o = 16; o; o >>= 1) v += __shfl_xor_sync(0xffffffffu, v, o);
    return v;
}

// ---------------- LN kernels ----------------
__global__ __launch_bounds__(256)
void ln_gather_kernel(const float* __restrict__ x,
                      const float* __restrict__ g, const float* __restrict__ bta) {
    int row  = (blockIdx.x * blockDim.x + threadIdx.x) >> 5;
    int lane = threadIdx.x & 31;
    if (row >= MROWS) return;
    int bw = row / NNC, n = row % NNC;
    const float* src = x + (size_t)map_token(bw, n) * DIMC;
    float v0 = src[lane], v1 = src[lane + 32], v2 = src[lane + 64];
    float mean = warp_sum(v0 + v1 + v2) * (1.f / 96.f);
    float d0 = v0 - mean, d1 = v1 - mean, d2 = v2 - mean;
    float var = warp_sum(d0 * d0 + d1 * d1 + d2 * d2) * (1.f / 96.f);
    float inv = rsqrtf(var + 1e-5f);
    float* dst = g_xw + (size_t)row * DIMC;
    dst[lane]      = d0 * inv * g[lane]      + bta[lane];
    dst[lane + 32] = d1 * inv * g[lane + 32] + bta[lane + 32];
    dst[lane + 64] = d2 * inv * g[lane + 64] + bta[lane + 64];
}

__global__ __launch_bounds__(256)
void ln_plain_kernel(const float* __restrict__ y,
                     const float* __restrict__ g, const float* __restrict__ bta,
                     float* __restrict__ out) {
    int row  = (blockIdx.x * blockDim.x + threadIdx.x) >> 5;
    int lane = threadIdx.x & 31;
    if (row >= MROWS) return;
    const float* src = y + (size_t)row * DIMC;
    float v0 = src[lane], v1 = src[lane + 32], v2 = src[lane + 64];
    float mean = warp_sum(v0 + v1 + v2) * (1.f / 96.f);
    float d0 = v0 - mean, d1 = v1 - mean, d2 = v2 - mean;
    float var = warp_sum(d0 * d0 + d1 * d1 + d2 * d2) * (1.f / 96.f);
    float inv = rsqrtf(var + 1e-5f);
    float* dst = out + (size_t)row * DIMC;
    dst[lane]      = d0 * inv * g[lane]      + bta[lane];
    dst[lane + 32] = d1 * inv * g[lane + 32] + bta[lane + 32];
    dst[lane + 64] = d2 * inv * g[lane + 64] + bta[lane + 64];
}

// ---------------- TF32x3 tensor-core GEMM ----------------
// C(MxN) = A(MxK) @ B(KxN) + epilogue, fp32-equivalent precision via hi/lo split.
// Block tile 128x96x16, 256 threads (8 warps, 4(M) x 2(N)), warp tile 32x48.
// MODE 0: +bias            (QKV)
// MODE 1: +bias, scatter row->token, += res  (proj + residual-1)
// MODE 2: +bias, exact GELU                  (fc1)
// MODE 3: +bias, += res                      (fc2 + residual-2)

__device__ __forceinline__ uint2 split_tf32(float x) {
    unsigned h, l;
    asm("cvt.rna.tf32.f32 %0, %1;" : "=r"(h) : "f"(x));
    float r = x - __uint_as_float(h);
    asm("cvt.rna.tf32.f32 %0, %1;" : "=r"(l) : "f"(r));
    return make_uint2(h, l);
}

__device__ __forceinline__ void mma8(float c[4],
                                     unsigned a0, unsigned a1, unsigned a2, unsigned a3,
                                     unsigned b0, unsigned b1) {
    asm volatile("mma.sync.aligned.m16n8k8.row.col.f32.tf32.tf32.f32 "
                 "{%0,%1,%2,%3}, {%4,%5,%6,%7}, {%8,%9}, {%0,%1,%2,%3};\n"
                 : "+f"(c[0]), "+f"(c[1]), "+f"(c[2]), "+f"(c[3])
                 : "r"(a0), "r"(a1), "r"(a2), "r"(a3), "r"(b0), "r"(b1));
}

template<int MODE>
__global__ __launch_bounds__(256, 2)
void gemm_tc(const float* __restrict__ A, const float* __restrict__ Bw,
             const float* __restrict__ bias, const float* __restrict__ res,
             float* __restrict__ out, int N, int K) {
    __shared__ uint2 As2[16][132];   // [k][m] hi/lo
    __shared__ uint2 Bs2[16][100];   // [k][n] hi/lo

    const int tid  = threadIdx.x;
    const int wid  = tid >> 5, lane = tid & 31;
    const int gid  = lane >> 2, tig = lane & 3;
    const int wm   = (wid >> 1) * 32;
    const int wn   = (wid & 1) * 48;
    const int m0   = blockIdx.y * 128;
    const int n0   = blockIdx.x * 96;

    // staging indices
    const int arow = tid >> 1;
    const int akk  = (tid & 1) * 8;
    const int bk0  = tid / 24,         bn0 = (tid % 24) * 4;
    const int bi1  = tid + 256;
    const int bk1  = bi1 / 24,         bn1 = (bi1 % 24) * 4;
    const bool bhas1 = (bi1 < 384);

    float acc[2][6][4];
    #pragma unroll
    for (int i = 0; i < 2; i++)
        #pragma unroll
        for (int j = 0; j < 6; j++)
            #pragma unroll
            for (int r = 0; r < 4; r++) acc[i][j][r] = 0.f;

    const float* Abase = A + (size_t)(m0 + arow) * K + akk;

    // prefetch tile 0
    float4 av0 = *(const float4*)(Abase);
    float4 av1 = *(const float4*)(Abase + 4);
    float4 bv0 = *(const float4*)(Bw + (size_t)bk0 * N + n0 + bn0);
    float4 bv1 = bhas1 ? *(const float4*)(Bw + (size_t)bk1 * N + n0 + bn1)
                       : make_float4(0.f, 0.f, 0.f, 0.f);

    const int T = K >> 4;
    for (int t = 0; t < T; t++) {
        // split + store staged tile
        As2[akk + 0][arow] = split_tf32(av0.x);
        As2[akk + 1][arow] = split_tf32(av0.y);
        As2[akk + 2][arow] = split_tf32(av0.z);
        As2[akk + 3][arow] = split_tf32(av0.w);
        As2[akk + 4][arow] = split_tf32(av1.x);
        As2[akk + 5][arow] = split_tf32(av1.y);
        As2[akk + 6][arow] = split_tf32(av1.z);
        As2[akk + 7][arow] = split_tf32(av1.w);
        Bs2[bk0][bn0 + 0] = split_tf32(bv0.x);
        Bs2[bk0][bn0 + 1] = split_tf32(bv0.y);
        Bs2[bk0][bn0 + 2] = split_tf32(bv0.z);
        Bs2[bk0][bn0 + 3] = split_tf32(bv0.w);
        if (bhas1) {
            Bs2[bk1][bn1 + 0] = split_tf32(bv1.x);
            Bs2[bk1][bn1 + 1] = split_tf32(bv1.y);
            Bs2[bk1][bn1 + 2] = split_tf32(bv1.z);
            Bs2[bk1][bn1 + 3] = split_tf32(bv1.w);
        }
        __syncthreads();

        // prefetch next tile (LDG overlapped with MMA below)
        if (t + 1 < T) {
            const int k0 = (t + 1) << 4;
            av0 = *(const float4*)(Abase + k0);
            av1 = *(const float4*)(Abase + k0 + 4);
            bv0 = *(const float4*)(Bw + (size_t)(k0 + bk0) * N + n0 + bn0);
            if (bhas1)
                bv1 = *(const float4*)(Bw + (size_t)(k0 + bk1) * N + n0 + bn1);
        }

        // 2 k-steps of 8
        #pragma unroll
        for (int ks = 0; ks < 2; ks++) {
            const int kk = ks * 8;
            uint2 af[2][4];
            #pragma unroll
            for (int mt = 0; mt < 2; mt++)
                #pragma unroll
                for (int r = 0; r < 4; r++)
                    af[mt][r] = As2[kk + tig + (r >> 1) * 4][wm + mt * 16 + gid + (r & 1) * 8];
            uint2 bf[6][2];
            #pragma unroll
            for (int nt = 0; nt < 6; nt++)
                #pragma unroll
                for (int r = 0; r < 2; r++)
                    bf[nt][r] = Bs2[kk + tig + r * 4][wn + nt * 8 + gid];

            #pragma unroll
            for (int mt = 0; mt < 2; mt++)
                #pragma unroll
                for (int nt = 0; nt < 6; nt++) {
                    float* c = acc[mt][nt];
                    mma8(c, af[mt][0].x, af[mt][1].x, af[mt][2].x, af[mt][3].x,
                            bf[nt][0].x, bf[nt][1].x);
                    mma8(c, af[mt][0].x, af[mt][1].x, af[mt][2].x, af[mt][3].x,
                            bf[nt][0].y, bf[nt][1].y);
                    mma8(c, af[mt][0].y, af[mt][1].y, af[mt][2].y, af[mt][3].y,
                            bf[nt][0].x, bf[nt][1].x);
                }
        }
        __syncthreads();
    }

    // ------------- epilogue -------------
    float bb[6][2];
    #pragma unroll
    for (int nt = 0; nt < 6; nt++) {
        int c = n0 + wn + nt * 8 + tig * 2;
        bb[nt][0] = bias[c];
        bb[nt][1] = bias[c + 1];
    }

    #pragma unroll
    for (int mt = 0; mt < 2; mt++) {
        #pragma unroll
        for (int half = 0; half < 2; half++) {
            int r = m0 + wm + mt * 16 + gid + half * 8;
            size_t orow;
            if (MODE == 1) orow = (size_t)map_token(r / NNC, r % NNC);
            else           orow = (size_t)r;
            float*       op = out + orow * N + n0 + wn + tig * 2;
            const float* rp = (MODE == 1 || MODE == 3) ? (res + orow * N + n0 + wn + tig * 2)
                                                       : nullptr;
            #pragma unroll
            for (int nt = 0; nt < 6; nt++) {
                float v0 = acc[mt][nt][half * 2 + 0] + bb[nt][0];
                float v1 = acc[mt][nt][half * 2 + 1] + bb[nt][1];
                if (MODE == 2) {
                    v0 = 0.5f * v0 * (1.0f + erff(v0 * 0.70710678118654752f));
                    v1 = 0.5f * v1 * (1.0f + erff(v1 * 0.70710678118654752f));
                }
                if (MODE == 1 || MODE == 3) {
                    v0 += rp[nt * 8];
                    v1 += rp[nt * 8 + 1];
                }
                *(float2*)(op + nt * 8) = make_float2(v0, v1);
            }
        }
    }
}

// ---------------- windowed attention (unchanged from R1) ----------------
__global__ __launch_bounds__(192)
void attn_kernel(const float* __restrict__ qkv, const float* __restrict__ rpb,
                 float* __restrict__ attno) {
    __shared__ float ks[NHC][NNC * HEADC];
    __shared__ float vs[NHC][NNC * HEADC];
    __shared__ float btab[169 * NHC];
    __shared__ int   regn[NNC];

    int bw   = blockIdx.x;
    int base = bw * NNC;
    int tid  = threadIdx.x;

    for (int idx = tid; idx < NHC * NNC * HEADC; idx += 192) {
        int h = idx / (NNC * HEADC);
        int r = idx % (NNC * HEADC);
        int m = r >> 5, d = r & 31;
        const float* p = qkv + (size_t)(base + m) * (3 * DIMC);
        ks[h][r] = p[DIMC     + h * HEADC + d];
        vs[h][r] = p[2 * DIMC + h * HEADC + d];
    }
    for (int i = tid; i < 169 * NHC; i += 192) btab[i] = rpb[i];
    for (int i = tid; i < NNC; i += 192) {
        if (i < PC) { regn[i] = -1; }
        else {
            int p = i - PC;
            int r = p / 7, c = p % 7;
            int w = bw & 63;
            int gh = (w >> 3) * 7 + r;
            int gw = (w & 7) * 7 + c;
            int rh = gh < 49 ? 0 : (gh < 53 ? 1 : 2);
            int rw = gw < 49 ? 0 : (gw < 53 ? 1 : 2);
            regn[i] = rh * 3 + rw;
        }
    }
    __syncthreads();

    int head = tid / 64;
    int t    = tid % 64;
    if (t >= NNC) return;

    const float4* qp = (const float4*)(qkv + (size_t)(base + t) * (3 * DIMC) + head * HEADC);
    float4 q4[8];
    #pragma unroll
    for (int j = 0; j < 8; j++) {
        q4[j] = qp[j];
        q4[j].x *= SCALEC; q4[j].y *= SCALEC; q4[j].z *= SCALEC; q4[j].w *= SCALEC;
    }

    bool feat = (t >= PC);
    int rt = 0, ct = 0, myreg = -1;
    if (feat) { rt = (t - PC) / 7; ct = (t - PC) % 7; myreg = regn[t]; }

    const float* kh = ks[head];
    float s[NNC];
    #pragma unroll
    for (int m = 0; m < NNC; m++) {
        const float4* k4 = (const float4*)(kh + m * HEADC);
        float a = 0.f;
        #pragma unroll
        for (int j = 0; j < 8; j++) {
            float4 kk = k4[j];
            a += q4[j].x * kk.x + q4[j].y * kk.y + q4[j].z * kk.z + q4[j].w * kk.w;
        }
        float badd = 0.f;
        if (feat && m >= PC) {
            const int rm = (m - PC) / 7, cm = (m - PC) % 7;
            int idx = (rt - rm + 6) * 13 + (ct - cm + 6);
            badd = btab[idx * NHC + head];
            if (regn[m] != myreg) badd -= 100.f;
        }
        s[m] = a + badd;
    }

    float mx = s[0];
    #pragma unroll
    for (int m = 1; m < NNC; m++) mx = fmaxf(mx, s[m]);
    float sum = 0.f;
    #pragma unroll
    for (int m = 0; m < NNC; m++) { s[m] = __expf(s[m] - mx); sum += s[m]; }
    float inv = 1.0f / sum;

    float acc[HEADC];
    #pragma unroll
    for (int d = 0; d < HEADC; d++) acc[d] = 0.f;
    const float* vh = vs[head];
    #pragma unroll
    for (int m = 0; m < NNC; m++) {
        float pm = s[m] * inv;
        const float4* v4 = (const float4*)(vh + m * HEADC);
        #pragma unroll
        for (int j = 0; j < 8; j++) {
            float4 vv = v4[j];
            acc[4 * j + 0] += pm * vv.x;
            acc[4 * j + 1] += pm * vv.y;
            acc[4 * j + 2] += pm * vv.z;
            acc[4 * j + 3] += pm * vv.w;
        }
    }

    float4* op = (float4*)(attno + (size_t)(base + t) * DIMC + head * HEADC);
    #pragma unroll
    for (int j = 0; j < 8; j++)
        op[j] = make_float4(acc[4 * j], acc[4 * j + 1], acc[4 * j + 2], acc[4 * j + 3]);
}

// ---------------- launch ----------------
extern "C" void kernel_launch(void* const* d_in, const int* in_sizes, int n_in,
                              void* d_out, int out_size) {
    const float* x       = (const float*)d_in[0];
    const float* norm1_g = (const float*)d_in[1];
    const float* norm1_b = (const float*)d_in[2];
    const float* qkv_w   = (const float*)d_in[3];
    const float* qkv_b   = (const float*)d_in[4];
    const float* rpb     = (const float*)d_in[5];
    const float* proj_w  = (const float*)d_in[6];
    const float* proj_b  = (const float*)d_in[7];
    const float* norm2_g = (const float*)d_in[8];
    const float* norm2_b = (const float*)d_in[9];
    const float* fc1_w   = (const float*)d_in[10];
    const float* fc1_b   = (const float*)d_in[11];
    const float* fc2_w   = (const float*)d_in[12];
    const float* fc2_b   = (const float*)d_in[13];
    float* out = (float*)d_out;

    float *p_xw, *p_qkv, *p_attno, *p_y, *p_yn, *p_h;
    cudaGetSymbolAddress((void**)&p_xw,    g_xw);
    cudaGetSymbolAddress((void**)&p_qkv,   g_qkv);
    cudaGetSymbolAddress((void**)&p_attno, g_attno);
    cudaGetSymbolAddress((void**)&p_y,     g_y);
    cudaGetSymbolAddress((void**)&p_yn,    g_yn);
    cudaGetSymbolAddress((void**)&p_h,     g_h);

    const int lnBlocks = (MROWS * 32 + 255) / 256;
    const int MB = MROWS / 128;   // 1728

    // 1. LN1 + window gather
    ln_gather_kernel<<<lnBlocks, 256>>>(x, norm1_g, norm1_b);
    // 2. QKV GEMM  (N=288, K=96)
    gemm_tc<0><<<dim3(3, MB), 256>>>(p_xw, qkv_w, qkv_b, nullptr, p_qkv, 288, 96);
    // 3. windowed attention
    attn_kernel<<<BATCHC * NWC, 192>>>(p_qkv, rpb, p_attno);
    // 4. proj GEMM + scatter + residual-1  (N=96, K=96)
    gemm_tc<1><<<dim3(1, MB), 256>>>(p_attno, proj_w, proj_b, x, p_y, 96, 96);
    // 5. LN2
    ln_plain_kernel<<<lnBlocks, 256>>>(p_y, norm2_g, norm2_b, p_yn);
    // 6. fc1 + GELU  (N=384, K=96)
    gemm_tc<2><<<dim3(4, MB), 256>>>(p_yn, fc1_w, fc1_b, nullptr, p_h, 384, 96);
    // 7. fc2 + residual-2 -> d_out  (N=96, K=384)
    gemm_tc<3><<<dim3(1, MB), 256>>>(p_h, fc2_w, fc2_b, p_y, out, 96, 384);
}

// round 3
// speedup vs baseline: 1.4087x; 1.2442x over previous
#include <cuda_runtime.h>
#include <cuda_bf16.h>
#include <math.h>

// ---------------- problem constants ----------------
#define DIMC    96
#define NHC     3
#define HEADC   32
#define WSC     7
#define SHIFTC  3
#define PC      5
#define HC      56
#define NWC     64
#define TPC     320
#define NNC     54
#define BATCHC  64
#define TOKC    3456
#define MROWS   (BATCHC * NWC * NNC)   // 221184
#define HIDC    384
#define SCALEC  0.17677669529663687f

// ---------------- scratch ----------------
__device__ float g_xw   [MROWS * DIMC];
__device__ float g_qkv  [(size_t)MROWS * 3 * DIMC];
__device__ float g_attno[MROWS * DIMC];
__device__ float g_y    [MROWS * DIMC];
__device__ float g_yn   [MROWS * DIMC];
__device__ float g_h    [(size_t)MROWS * HIDC];

__device__ __forceinline__ int map_token(int bw, int n) {
    int b = bw >> 6;
    int w = bw & 63;
    int tok;
    if (n < PC) {
        tok = w * PC + n;
    } else {
        int p  = n - PC;
        int r  = p / 7, c = p % 7;
        int wh = w >> 3, ww = w & 7;
        int hr = wh * 7 + r + SHIFTC; if (hr >= HC) hr -= HC;
        int wc = ww * 7 + c + SHIFTC; if (wc >= HC) wc -= HC;
        tok = TPC + hr * HC + wc;
    }
    return b * TOKC + tok;
}

__device__ __forceinline__ float warp_sum(float v) {
    #pragma unroll
    for (int o = 16; o; o >>= 1) v += __shfl_xor_sync(0xffffffffu, v, o);
    return v;
}

// ---------------- LN kernels ----------------
__global__ __launch_bounds__(256)
void ln_gather_kernel(const float* __restrict__ x,
                      const float* __restrict__ g, const float* __restrict__ bta) {
    int row  = (blockIdx.x * blockDim.x + threadIdx.x) >> 5;
    int lane = threadIdx.x & 31;
    if (row >= MROWS) return;
    int bw = row / NNC, n = row % NNC;
    const float* src = x + (size_t)map_token(bw, n) * DIMC;
    float v0 = src[lane], v1 = src[lane + 32], v2 = src[lane + 64];
    float mean = warp_sum(v0 + v1 + v2) * (1.f / 96.f);
    float d0 = v0 - mean, d1 = v1 - mean, d2 = v2 - mean;
    float var = warp_sum(d0 * d0 + d1 * d1 + d2 * d2) * (1.f / 96.f);
    float inv = rsqrtf(var + 1e-5f);
    float* dst = g_xw + (size_t)row * DIMC;
    dst[lane]      = d0 * inv * g[lane]      + bta[lane];
    dst[lane + 32] = d1 * inv * g[lane + 32] + bta[lane + 32];
    dst[lane + 64] = d2 * inv * g[lane + 64] + bta[lane + 64];
}

__global__ __launch_bounds__(256)
void ln_plain_kernel(const float* __restrict__ y,
                     const float* __restrict__ g, const float* __restrict__ bta,
                     float* __restrict__ out) {
    int row  = (blockIdx.x * blockDim.x + threadIdx.x) >> 5;
    int lane = threadIdx.x & 31;
    if (row >= MROWS) return;
    const float* src = y + (size_t)row * DIMC;
    float v0 = src[lane], v1 = src[lane + 32], v2 = src[lane + 64];
    float mean = warp_sum(v0 + v1 + v2) * (1.f / 96.f);
    float d0 = v0 - mean, d1 = v1 - mean, d2 = v2 - mean;
    float var = warp_sum(d0 * d0 + d1 * d1 + d2 * d2) * (1.f / 96.f);
    float inv = rsqrtf(var + 1e-5f);
    float* dst = out + (size_t)row * DIMC;
    dst[lane]      = d0 * inv * g[lane]      + bta[lane];
    dst[lane + 32] = d1 * inv * g[lane + 32] + bta[lane + 32];
    dst[lane + 64] = d2 * inv * g[lane + 64] + bta[lane + 64];
}

// ---------------- BF16x3 tensor-core GEMM ----------------
// C = A(MxK) @ B(KxN) + epilogue, ~fp32 precision via bf16 hi/lo split:
//   A*B ~= Ah*Bh + Ah*Bl + Al*Bh   (missing Al*Bl ~ 2^-18 relative)
// Block tile 128x96x32, 256 threads (8 warps 4x2), warp tile 32x48,
// mma.sync.m16n8k16.bf16. Smem stores uint2{hi_pair, lo_pair}, 2 k-elems
// packed per 32-bit half -> fragment LDS are conflict-free LDS.64.

__device__ __forceinline__ uint2 split_bf16_pair(float x0, float x1) {
    // x0 = k-even element (low 16 bits), x1 = k-odd (high 16 bits)
    __nv_bfloat16 h0 = __float2bfloat16(x0);
    __nv_bfloat16 h1 = __float2bfloat16(x1);
    float r0 = x0 - __bfloat162float(h0);
    float r1 = x1 - __bfloat162float(h1);
    __nv_bfloat16 l0 = __float2bfloat16(r0);
    __nv_bfloat16 l1 = __float2bfloat16(r1);
    uint2 o;
    o.x = ((unsigned)__bfloat16_as_ushort(h1) << 16) | (unsigned)__bfloat16_as_ushort(h0);
    o.y = ((unsigned)__bfloat16_as_ushort(l1) << 16) | (unsigned)__bfloat16_as_ushort(l0);
    return o;
}

__device__ __forceinline__ void mma16(float c[4],
                                      unsigned a0, unsigned a1, unsigned a2, unsigned a3,
                                      unsigned b0, unsigned b1) {
    asm volatile("mma.sync.aligned.m16n8k16.row.col.f32.bf16.bf16.f32 "
                 "{%0,%1,%2,%3}, {%4,%5,%6,%7}, {%8,%9}, {%0,%1,%2,%3};\n"
                 : "+f"(c[0]), "+f"(c[1]), "+f"(c[2]), "+f"(c[3])
                 : "r"(a0), "r"(a1), "r"(a2), "r"(a3), "r"(b0), "r"(b1));
}

#define BKG 32   // k per block tile (16 k-pairs)

template<int MODE>
__global__ __launch_bounds__(256, 2)
void gemm_tc(const float* __restrict__ A, const float* __restrict__ Bw,
             const float* __restrict__ bias, const float* __restrict__ res,
             float* __restrict__ out, int N, int K) {
    __shared__ uint2 As2[16][132];   // [kpair][m]  stride 264 words == 8 mod 32
    __shared__ uint2 Bs2[16][100];   // [kpair][n]  stride 200 words == 8 mod 32

    const int tid  = threadIdx.x;
    const int wid  = tid >> 5, lane = tid & 31;
    const int gid  = lane >> 2, tig = lane & 3;
    const int wm   = (wid >> 1) * 32;
    const int wn   = (wid & 1) * 48;
    const int m0   = blockIdx.y * 128;
    const int n0   = blockIdx.x * 96;

    // A staging: row arow, 16 consecutive k at offset akk (2 lanes cover 128B)
    const int arow = tid >> 1;
    const int akk  = (tid & 1) * 16;
    // B staging: assignment i -> k-pair row kp, 4 columns at bn
    const int kp0 = tid / 24,           bn0 = (tid % 24) * 4;
    const int i1  = tid + 256;
    const bool has1 = (i1 < 384);
    const int kp1 = i1 / 24,            bn1 = (i1 % 24) * 4;

    float acc[2][6][4];
    #pragma unroll
    for (int i = 0; i < 2; i++)
        #pragma unroll
        for (int j = 0; j < 6; j++)
            #pragma unroll
            for (int r = 0; r < 4; r++) acc[i][j][r] = 0.f;

    const float* Abase = A + (size_t)(m0 + arow) * K + akk;

    // prefetch tile 0
    float4 av[4];
    #pragma unroll
    for (int j = 0; j < 4; j++) av[j] = *(const float4*)(Abase + j * 4);
    float4 b0e = *(const float4*)(Bw + (size_t)(2 * kp0)     * N + n0 + bn0);
    float4 b0o = *(const float4*)(Bw + (size_t)(2 * kp0 + 1) * N + n0 + bn0);
    float4 b1e, b1o;
    if (has1) {
        b1e = *(const float4*)(Bw + (size_t)(2 * kp1)     * N + n0 + bn1);
        b1o = *(const float4*)(Bw + (size_t)(2 * kp1 + 1) * N + n0 + bn1);
    }

    const int T = K / BKG;
    for (int t = 0; t < T; t++) {
        // ---- split + store staged tile ----
        {
            const int kb = akk >> 1;
            As2[kb + 0][arow] = split_bf16_pair(av[0].x, av[0].y);
            As2[kb + 1][arow] = split_bf16_pair(av[0].z, av[0].w);
            As2[kb + 2][arow] = split_bf16_pair(av[1].x, av[1].y);
            As2[kb + 3][arow] = split_bf16_pair(av[1].z, av[1].w);
            As2[kb + 4][arow] = split_bf16_pair(av[2].x, av[2].y);
            As2[kb + 5][arow] = split_bf16_pair(av[2].z, av[2].w);
            As2[kb + 6][arow] = split_bf16_pair(av[3].x, av[3].y);
            As2[kb + 7][arow] = split_bf16_pair(av[3].z, av[3].w);
            Bs2[kp0][bn0 + 0] = split_bf16_pair(b0e.x, b0o.x);
            Bs2[kp0][bn0 + 1] = split_bf16_pair(b0e.y, b0o.y);
            Bs2[kp0][bn0 + 2] = split_bf16_pair(b0e.z, b0o.z);
            Bs2[kp0][bn0 + 3] = split_bf16_pair(b0e.w, b0o.w);
            if (has1) {
                Bs2[kp1][bn1 + 0] = split_bf16_pair(b1e.x, b1o.x);
                Bs2[kp1][bn1 + 1] = split_bf16_pair(b1e.y, b1o.y);
                Bs2[kp1][bn1 + 2] = split_bf16_pair(b1e.z, b1o.z);
                Bs2[kp1][bn1 + 3] = split_bf16_pair(b1e.w, b1o.w);
            }
        }
        __syncthreads();

        // ---- prefetch next tile (overlaps MMAs) ----
        if (t + 1 < T) {
            const int k0 = (t + 1) * BKG;
            #pragma unroll
            for (int j = 0; j < 4; j++) av[j] = *(const float4*)(Abase + k0 + j * 4);
            b0e = *(const float4*)(Bw + (size_t)(k0 + 2 * kp0)     * N + n0 + bn0);
            b0o = *(const float4*)(Bw + (size_t)(k0 + 2 * kp0 + 1) * N + n0 + bn0);
            if (has1) {
                b1e = *(const float4*)(Bw + (size_t)(k0 + 2 * kp1)     * N + n0 + bn1);
                b1o = *(const float4*)(Bw + (size_t)(k0 + 2 * kp1 + 1) * N + n0 + bn1);
            }
        }

        // ---- 2 k-steps of k16 ----
        #pragma unroll
        for (int ks = 0; ks < 2; ks++) {
            const int kb = ks * 8;
            uint2 af[2][4];
            #pragma unroll
            for (int mt = 0; mt < 2; mt++) {
                const int m = wm + mt * 16 + gid;
                af[mt][0] = As2[kb + tig    ][m];
                af[mt][1] = As2[kb + tig    ][m + 8];
                af[mt][2] = As2[kb + tig + 4][m];
                af[mt][3] = As2[kb + tig + 4][m + 8];
            }
            uint2 bf[6][2];
            #pragma unroll
            for (int nt = 0; nt < 6; nt++) {
                const int n = wn + nt * 8 + gid;
                bf[nt][0] = Bs2[kb + tig    ][n];
                bf[nt][1] = Bs2[kb + tig + 4][n];
            }
            #pragma unroll
            for (int mt = 0; mt < 2; mt++)
                #pragma unroll
                for (int nt = 0; nt < 6; nt++) {
                    float* c = acc[mt][nt];
                    mma16(c, af[mt][0].x, af[mt][1].x, af[mt][2].x, af[mt][3].x,
                             bf[nt][0].x, bf[nt][1].x);               // hi*hi
                    mma16(c, af[mt][0].x, af[mt][1].x, af[mt][2].x, af[mt][3].x,
                             bf[nt][0].y, bf[nt][1].y);               // hi*lo
                    mma16(c, af[mt][0].y, af[mt][1].y, af[mt][2].y, af[mt][3].y,
                             bf[nt][0].x, bf[nt][1].x);               // lo*hi
                }
        }
        __syncthreads();
    }

    // ------------- epilogue -------------
    float bb[6][2];
    #pragma unroll
    for (int nt = 0; nt < 6; nt++) {
        int c = n0 + wn + nt * 8 + tig * 2;
        bb[nt][0] = bias[c];
        bb[nt][1] = bias[c + 1];
    }

    #pragma unroll
    for (int mt = 0; mt < 2; mt++) {
        #pragma unroll
        for (int half = 0; half < 2; half++) {
            int r = m0 + wm + mt * 16 + gid + half * 8;
            size_t orow;
            if (MODE == 1) orow = (size_t)map_token(r / NNC, r % NNC);
            else           orow = (size_t)r;
            float*       op = out + orow * N + n0 + wn + tig * 2;
            const float* rp = (MODE == 1 || MODE == 3) ? (res + orow * N + n0 + wn + tig * 2)
                                                       : nullptr;
            #pragma unroll
            for (int nt = 0; nt < 6; nt++) {
                float v0 = acc[mt][nt][half * 2 + 0] + bb[nt][0];
                float v1 = acc[mt][nt][half * 2 + 1] + bb[nt][1];
                if (MODE == 2) {
                    v0 = 0.5f * v0 * (1.0f + erff(v0 * 0.70710678118654752f));
                    v1 = 0.5f * v1 * (1.0f + erff(v1 * 0.70710678118654752f));
                }
                if (MODE == 1 || MODE == 3) {
                    v0 += rp[nt * 8];
                    v1 += rp[nt * 8 + 1];
                }
                *(float2*)(op + nt * 8) = make_float2(v0, v1);
            }
        }
    }
}

// ---------------- windowed attention (unchanged) ----------------
__global__ __launch_bounds__(192)
void attn_kernel(const float* __restrict__ qkv, const float* __restrict__ rpb,
                 float* __restrict__ attno) {
    __shared__ float ks[NHC][NNC * HEADC];
    __shared__ float vs[NHC][NNC * HEADC];
    __shared__ float btab[169 * NHC];
    __shared__ int   regn[NNC];

    int bw   = blockIdx.x;
    int base = bw * NNC;
    int tid  = threadIdx.x;

    for (int idx = tid; idx < NHC * NNC * HEADC; idx += 192) {
        int h = idx / (NNC * HEADC);
        int r = idx % (NNC * HEADC);
        int m = r >> 5, d = r & 31;
        const float* p = qkv + (size_t)(base + m) * (3 * DIMC);
        ks[h][r] = p[DIMC     + h * HEADC + d];
        vs[h][r] = p[2 * DIMC + h * HEADC + d];
    }
    for (int i = tid; i < 169 * NHC; i += 192) btab[i] = rpb[i];
    for (int i = tid; i < NNC; i += 192) {
        if (i < PC) { regn[i] = -1; }
        else {
            int p = i - PC;
            int r = p / 7, c = p % 7;
            int w = bw & 63;
            int gh = (w >> 3) * 7 + r;
            int gw = (w & 7) * 7 + c;
            int rh = gh < 49 ? 0 : (gh < 53 ? 1 : 2);
            int rw = gw < 49 ? 0 : (gw < 53 ? 1 : 2);
            regn[i] = rh * 3 + rw;
        }
    }
    __syncthreads();

    int head = tid / 64;
    int t    = tid % 64;
    if (t >= NNC) return;

    const float4* qp = (const float4*)(qkv + (size_t)(base + t) * (3 * DIMC) + head * HEADC);
    float4 q4[8];
    #pragma unroll
    for (int j = 0; j < 8; j++) {
        q4[j] = qp[j];
        q4[j].x *= SCALEC; q4[j].y *= SCALEC; q4[j].z *= SCALEC; q4[j].w *= SCALEC;
    }

    bool feat = (t >= PC);
    int rt = 0, ct = 0, myreg = -1;
    if (feat) { rt = (t - PC) / 7; ct = (t - PC) % 7; myreg = regn[t]; }

    const float* kh = ks[head];
    float s[NNC];
    #pragma unroll
    for (int m = 0; m < NNC; m++) {
        const float4* k4 = (const float4*)(kh + m * HEADC);
        float a = 0.f;
        #pragma unroll
        for (int j = 0; j < 8; j++) {
            float4 kk = k4[j];
            a += q4[j].x * kk.x + q4[j].y * kk.y + q4[j].z * kk.z + q4[j].w * kk.w;
        }
        float badd = 0.f;
        if (feat && m >= PC) {
            const int rm = (m - PC) / 7, cm = (m - PC) % 7;
            int idx = (rt - rm + 6) * 13 + (ct - cm + 6);
            badd = btab[idx * NHC + head];
            if (regn[m] != myreg) badd -= 100.f;
        }
        s[m] = a + badd;
    }

    float mx = s[0];
    #pragma unroll
    for (int m = 1; m < NNC; m++) mx = fmaxf(mx, s[m]);
    float sum = 0.f;
    #pragma unroll
    for (int m = 0; m < NNC; m++) { s[m] = __expf(s[m] - mx); sum += s[m]; }
    float inv = 1.0f / sum;

    float acc[HEADC];
    #pragma unroll
    for (int d = 0; d < HEADC; d++) acc[d] = 0.f;
    const float* vh = vs[head];
    #pragma unroll
    for (int m = 0; m < NNC; m++) {
        float pm = s[m] * inv;
        const float4* v4 = (const float4*)(vh + m * HEADC);
        #pragma unroll
        for (int j = 0; j < 8; j++) {
            float4 vv = v4[j];
            acc[4 * j + 0] += pm * vv.x;
            acc[4 * j + 1] += pm * vv.y;
            acc[4 * j + 2] += pm * vv.z;
            acc[4 * j + 3] += pm * vv.w;
        }
    }

    float4* op = (float4*)(attno + (size_t)(base + t) * DIMC + head * HEADC);
    #pragma unroll
    for (int j = 0; j < 8; j++)
        op[j] = make_float4(acc[4 * j], acc[4 * j + 1], acc[4 * j + 2], acc[4 * j + 3]);
}

// ---------------- launch ----------------
extern "C" void kernel_launch(void* const* d_in, const int* in_sizes, int n_in,
                              void* d_out, int out_size) {
    const float* x       = (const float*)d_in[0];
    const float* norm1_g = (const float*)d_in[1];
    const float* norm1_b = (const float*)d_in[2];
    const float* qkv_w   = (const float*)d_in[3];
    const float* qkv_b   = (const float*)d_in[4];
    const float* rpb     = (const float*)d_in[5];
    const float* proj_w  = (const float*)d_in[6];
    const float* proj_b  = (const float*)d_in[7];
    const float* norm2_g = (const float*)d_in[8];
    const float* norm2_b = (const float*)d_in[9];
    const float* fc1_w   = (const float*)d_in[10];
    const float* fc1_b   = (const float*)d_in[11];
    const float* fc2_w   = (const float*)d_in[12];
    const float* fc2_b   = (const float*)d_in[13];
    float* out = (float*)d_out;

    float *p_xw, *p_qkv, *p_attno, *p_y, *p_yn, *p_h;
    cudaGetSymbolAddress((void**)&p_xw,    g_xw);
    cudaGetSymbolAddress((void**)&p_qkv,   g_qkv);
    cudaGetSymbolAddress((void**)&p_attno, g_attno);
    cudaGetSymbolAddress((void**)&p_y,     g_y);
    cudaGetSymbolAddress((void**)&p_yn,    g_yn);
    cudaGetSymbolAddress((void**)&p_h,     g_h);

    const int lnBlocks = (MROWS * 32 + 255) / 256;
    const int MB = MROWS / 128;   // 1728

    ln_gather_kernel<<<lnBlocks, 256>>>(x, norm1_g, norm1_b);
    gemm_tc<0><<<dim3(3, MB), 256>>>(p_xw, qkv_w, qkv_b, nullptr, p_qkv, 288, 96);
    attn_kernel<<<BATCHC * NWC, 192>>>(p_qkv, rpb, p_attno);
    gemm_tc<1><<<dim3(1, MB), 256>>>(p_attno, proj_w, proj_b, x, p_y, 96, 96);
    ln_plain_kernel<<<lnBlocks, 256>>>(p_y, norm2_g, norm2_b, p_yn);
    gemm_tc<2><<<dim3(4, MB), 256>>>(p_yn, fc1_w, fc1_b, nullptr, p_h, 384, 96);
    gemm_tc<3><<<dim3(1, MB), 256>>>(p_h, fc2_w, fc2_b, p_y, out, 96, 384);
}

// round 4
// speedup vs baseline: 1.4811x; 1.0514x over previous
#include <cuda_runtime.h>
#include <cuda_bf16.h>
#include <math.h>

// ---------------- problem constants ----------------
#define DIMC    96
#define NHC     3
#define HEADC   32
#define WSC     7
#define SHIFTC  3
#define PC      5
#define HC      56
#define NWC     64
#define TPC     320
#define NNC     54
#define BATCHC  64
#define TOKC    3456
#define MROWS   (BATCHC * NWC * NNC)   // 221184
#define HIDC    384
#define SCALEC  0.17677669529663687f

// ---------------- scratch (split format: uint2{hi bf16 pair, lo bf16 pair}) ----------------
__device__ __align__(16) uint2 g_xw_sp   [MROWS * 48];            // LN1 out, window order
__device__ float               g_qkv     [(size_t)MROWS * 3 * DIMC];
__device__ __align__(16) uint2 g_attno_sp[MROWS * 48];            // attn out, window order
__device__ float               g_y       [MROWS * DIMC];          // residual stream (fp32)
__device__ __align__(16) uint2 g_yn_sp   [MROWS * 48];            // LN2 out
__device__ __align__(16) uint2 g_h_sp    [(size_t)MROWS * 192];   // fc1+GELU out
// pre-split weights [kpair][n]
__device__ __align__(16) uint2 g_wq_sp[48 * 288];
__device__ __align__(16) uint2 g_wp_sp[48 * 96];
__device__ __align__(16) uint2 g_w1_sp[48 * 384];
__device__ __align__(16) uint2 g_w2_sp[192 * 96];

__device__ __forceinline__ int map_token(int bw, int n) {
    int b = bw >> 6;
    int w = bw & 63;
    int tok;
    if (n < PC) {
        tok = w * PC + n;
    } else {
        int p  = n - PC;
        int r  = p / 7, c = p % 7;
        int wh = w >> 3, ww = w & 7;
        int hr = wh * 7 + r + SHIFTC; if (hr >= HC) hr -= HC;
        int wc = ww * 7 + c + SHIFTC; if (wc >= HC) wc -= HC;
        tok = TPC + hr * HC + wc;
    }
    return b * TOKC + tok;
}

__device__ __forceinline__ float warp_sum(float v) {
    #pragma unroll
    for (int o = 16; o; o >>= 1) v += __shfl_xor_sync(0xffffffffu, v, o);
    return v;
}

__device__ __forceinline__ uint2 split_bf16_pair(float x0, float x1) {
    __nv_bfloat16 h0 = __float2bfloat16(x0);
    __nv_bfloat16 h1 = __float2bfloat16(x1);
    float r0 = x0 - __bfloat162float(h0);
    float r1 = x1 - __bfloat162float(h1);
    __nv_bfloat16 l0 = __float2bfloat16(r0);
    __nv_bfloat16 l1 = __float2bfloat16(r1);
    uint2 o;
    o.x = ((unsigned)__bfloat16_as_ushort(h1) << 16) | (unsigned)__bfloat16_as_ushort(h0);
    o.y = ((unsigned)__bfloat16_as_ushort(l1) << 16) | (unsigned)__bfloat16_as_ushort(l0);
    return o;
}

// ---------------- weight pre-split ----------------
__global__ __launch_bounds__(256)
void split_w_kernel(const float* __restrict__ qkv_w, const float* __restrict__ proj_w,
                    const float* __restrict__ fc1_w, const float* __restrict__ fc2_w) {
    int i = blockIdx.x * blockDim.x + threadIdx.x;
    if (i < 13824) {
        int kp = i / 288, n = i % 288;
        g_wq_sp[i] = split_bf16_pair(qkv_w[(2 * kp) * 288 + n], qkv_w[(2 * kp + 1) * 288 + n]);
    } else if (i < 18432) {
        int j = i - 13824, kp = j / 96, n = j % 96;
        g_wp_sp[j] = split_bf16_pair(proj_w[(2 * kp) * 96 + n], proj_w[(2 * kp + 1) * 96 + n]);
    } else if (i < 36864) {
        int j = i - 18432, kp = j / 384, n = j % 384;
        g_w1_sp[j] = split_bf16_pair(fc1_w[(2 * kp) * 384 + n], fc1_w[(2 * kp + 1) * 384 + n]);
    } else if (i < 55296) {
        int j = i - 36864, kp = j / 96, n = j % 96;
        g_w2_sp[j] = split_bf16_pair(fc2_w[(2 * kp) * 96 + n], fc2_w[(2 * kp + 1) * 96 + n]);
    }
}

// ---------------- LN kernels (write split pairs) ----------------
__global__ __launch_bounds__(256)
void ln_gather_kernel(const float* __restrict__ x,
                      const float* __restrict__ g, const float* __restrict__ bta) {
    int row  = (blockIdx.x * blockDim.x + threadIdx.x) >> 5;
    int lane = threadIdx.x & 31;
    if (row >= MROWS) return;
    int bw = row / NNC, n = row % NNC;
    const float2* src2 = (const float2*)(x + (size_t)map_token(bw, n) * DIMC);
    float2 a0 = src2[lane];
    float2 a1 = make_float2(0.f, 0.f);
    if (lane < 16) a1 = src2[32 + lane];
    float s = a0.x + a0.y + a1.x + a1.y;
    float mean = warp_sum(s) * (1.f / 96.f);
    float d0x = a0.x - mean, d0y = a0.y - mean;
    float d1x = a1.x - mean, d1y = a1.y - mean;
    float vq = d0x * d0x + d0y * d0y + (lane < 16 ? d1x * d1x + d1y * d1y : 0.f);
    float var = warp_sum(vq) * (1.f / 96.f);
    float inv = rsqrtf(var + 1e-5f);
    const float2* g2 = (const float2*)g;
    const float2* b2 = (const float2*)bta;
    uint2* dst = g_xw_sp + (size_t)row * 48;
    float2 G = g2[lane], B = b2[lane];
    dst[lane] = split_bf16_pair(d0x * inv * G.x + B.x, d0y * inv * G.y + B.y);
    if (lane < 16) {
        float2 G1 = g2[32 + lane], B1 = b2[32 + lane];
        dst[32 + lane] = split_bf16_pair(d1x * inv * G1.x + B1.x, d1y * inv * G1.y + B1.y);
    }
}

__global__ __launch_bounds__(256)
void ln_plain_kernel(const float* __restrict__ y,
                     const float* __restrict__ g, const float* __restrict__ bta) {
    int row  = (blockIdx.x * blockDim.x + threadIdx.x) >> 5;
    int lane = threadIdx.x & 31;
    if (row >= MROWS) return;
    const float2* src2 = (const float2*)(y + (size_t)row * DIMC);
    float2 a0 = src2[lane];
    float2 a1 = make_float2(0.f, 0.f);
    if (lane < 16) a1 = src2[32 + lane];
    float s = a0.x + a0.y + a1.x + a1.y;
    float mean = warp_sum(s) * (1.f / 96.f);
    float d0x = a0.x - mean, d0y = a0.y - mean;
    float d1x = a1.x - mean, d1y = a1.y - mean;
    float vq = d0x * d0x + d0y * d0y + (lane < 16 ? d1x * d1x + d1y * d1y : 0.f);
    float var = warp_sum(vq) * (1.f / 96.f);
    float inv = rsqrtf(var + 1e-5f);
    const float2* g2 = (const float2*)g;
    const float2* b2 = (const float2*)bta;
    uint2* dst = g_yn_sp + (size_t)row * 48;
    float2 G = g2[lane], B = b2[lane];
    dst[lane] = split_bf16_pair(d0x * inv * G.x + B.x, d0y * inv * G.y + B.y);
    if (lane < 16) {
        float2 G1 = g2[32 + lane], B1 = b2[32 + lane];
        dst[32 + lane] = split_bf16_pair(d1x * inv * G1.x + B1.x, d1y * inv * G1.y + B1.y);
    }
}

// ---------------- BF16x3 tensor-core GEMM, pre-split operands, 2-stage pipeline ----------------
// A: uint2[row][kpair] (KP = K/2), B: uint2[kpair][n].
// Block tile 128x96x32, 8 warps (4x2), warp tile 32x48, m16n8k16 bf16.
// MODE 0: +bias -> float out                  (QKV)
// MODE 1: +bias, scatter, +=res -> float out  (proj)
// MODE 2: +bias, GELU -> split uint2 out      (fc1)
// MODE 3: +bias, +=res -> float out           (fc2)

__device__ __forceinline__ void mma16(float c[4],
                                      unsigned a0, unsigned a1, unsigned a2, unsigned a3,
                                      unsigned b0, unsigned b1) {
    asm volatile("mma.sync.aligned.m16n8k16.row.col.f32.bf16.bf16.f32 "
                 "{%0,%1,%2,%3}, {%4,%5,%6,%7}, {%8,%9}, {%0,%1,%2,%3};\n"
                 : "+f"(c[0]), "+f"(c[1]), "+f"(c[2]), "+f"(c[3])
                 : "r"(a0), "r"(a1), "r"(a2), "r"(a3), "r"(b0), "r"(b1));
}

#define GEMM_SMEM ((2 * 16 * 132 + 2 * 16 * 100) * 8)   // 59392 bytes

template<int MODE>
__global__ __launch_bounds__(256, 2)
void gemm_tc(const uint2* __restrict__ A, const uint2* __restrict__ Bw,
             const float* __restrict__ bias, const float* __restrict__ res,
             float* __restrict__ out, uint2* __restrict__ outp, int N, int K) {
    extern __shared__ uint2 smemu[];
    uint2 (*As2)[16][132] = reinterpret_cast<uint2(*)[16][132]>(smemu);
    uint2 (*Bs2)[16][100] = reinterpret_cast<uint2(*)[16][100]>(smemu + 2 * 16 * 132);

    const int tid  = threadIdx.x;
    const int wid  = tid >> 5, lane = tid & 31;
    const int gid  = lane >> 2, tig = lane & 3;
    const int wm   = (wid >> 1) * 32;
    const int wn   = (wid & 1) * 48;
    const int m0   = blockIdx.y * 128;
    const int n0   = blockIdx.x * 96;
    const int KP   = K >> 1;

    // staging assignments
    int arow[4], akp[4];
    const uint2* aPtr[4];
    #pragma unroll
    for (int j = 0; j < 4; j++) {
        int c = tid + 256 * j;
        arow[j] = c >> 3;
        akp[j]  = (c & 7) * 2;
        aPtr[j] = A + (size_t)(m0 + arow[j]) * KP + akp[j];
    }
    int bkp[3], bn2[3];
    const uint2* bPtr[3];
    #pragma unroll
    for (int j = 0; j < 3; j++) {
        int c = tid + 256 * j;
        bkp[j] = c / 48;
        bn2[j] = (c % 48) * 2;
        bPtr[j] = Bw + (size_t)bkp[j] * N + n0 + bn2[j];
    }

    float acc[2][6][4];
    #pragma unroll
    for (int i = 0; i < 2; i++)
        #pragma unroll
        for (int j = 0; j < 6; j++)
            #pragma unroll
            for (int r = 0; r < 4; r++) acc[i][j][r] = 0.f;

    uint4 aR[4], bR[3];
    #pragma unroll
    for (int j = 0; j < 4; j++) aR[j] = *(const uint4*)(aPtr[j]);
    #pragma unroll
    for (int j = 0; j < 3; j++) bR[j] = *(const uint4*)(bPtr[j]);

    // store stage 0
    #pragma unroll
    for (int j = 0; j < 4; j++) {
        As2[0][akp[j]][arow[j]]     = make_uint2(aR[j].x, aR[j].y);
        As2[0][akp[j] + 1][arow[j]] = make_uint2(aR[j].z, aR[j].w);
    }
    #pragma unroll
    for (int j = 0; j < 3; j++)
        *(uint4*)&Bs2[0][bkp[j]][bn2[j]] = bR[j];
    __syncthreads();

    const int T = K >> 5;   // k-tiles of 32
    for (int t = 0; t < T; t++) {
        const int s = t & 1;
        if (t + 1 < T) {
            const int kt = 16 * (t + 1);
            #pragma unroll
            for (int j = 0; j < 4; j++) aR[j] = *(const uint4*)(aPtr[j] + kt);
            #pragma unroll
            for (int j = 0; j < 3; j++) bR[j] = *(const uint4*)(bPtr[j] + (size_t)kt * N);
        }

        // ---- MMA on stage s ----
        #pragma unroll
        for (int ks = 0; ks < 2; ks++) {
            const int kb = ks * 8;
            uint2 af[2][4];
            #pragma unroll
            for (int mt = 0; mt < 2; mt++) {
                const int m = wm + mt * 16 + gid;
                af[mt][0] = As2[s][kb + tig    ][m];
                af[mt][1] = As2[s][kb + tig    ][m + 8];
                af[mt][2] = As2[s][kb + tig + 4][m];
                af[mt][3] = As2[s][kb + tig + 4][m + 8];
            }
            uint2 bf[6][2];
            #pragma unroll
            for (int nt = 0; nt < 6; nt++) {
                const int n = wn + nt * 8 + gid;
                bf[nt][0] = Bs2[s][kb + tig    ][n];
                bf[nt][1] = Bs2[s][kb + tig + 4][n];
            }
            #pragma unroll
            for (int mt = 0; mt < 2; mt++)
                #pragma unroll
                for (int nt = 0; nt < 6; nt++) {
                    float* c = acc[mt][nt];
                    mma16(c, af[mt][0].x, af[mt][1].x, af[mt][2].x, af[mt][3].x,
                             bf[nt][0].x, bf[nt][1].x);               // hi*hi
                    mma16(c, af[mt][0].x, af[mt][1].x, af[mt][2].x, af[mt][3].x,
                             bf[nt][0].y, bf[nt][1].y);               // hi*lo
                    mma16(c, af[mt][0].y, af[mt][1].y, af[mt][2].y, af[mt][3].y,
                             bf[nt][0].x, bf[nt][1].x);               // lo*hi
                }
        }

        // ---- stage t+1 into the other buffer ----
        if (t + 1 < T) {
            const int sn = (t + 1) & 1;
            #pragma unroll
            for (int j = 0; j < 4; j++) {
                As2[sn][akp[j]][arow[j]]     = make_uint2(aR[j].x, aR[j].y);
                As2[sn][akp[j] + 1][arow[j]] = make_uint2(aR[j].z, aR[j].w);
            }
            #pragma unroll
            for (int j = 0; j < 3; j++)
                *(uint4*)&Bs2[sn][bkp[j]][bn2[j]] = bR[j];
        }
        __syncthreads();
    }

    // ------------- epilogue -------------
    float bb[6][2];
    #pragma unroll
    for (int nt = 0; nt < 6; nt++) {
        int c = n0 + wn + nt * 8 + tig * 2;
        bb[nt][0] = bias[c];
        bb[nt][1] = bias[c + 1];
    }

    #pragma unroll
    for (int mt = 0; mt < 2; mt++) {
        #pragma unroll
        for (int half = 0; half < 2; half++) {
            int r = m0 + wm + mt * 16 + gid + half * 8;
            size_t orow;
            if (MODE == 1) orow = (size_t)map_token(r / NNC, r % NNC);
            else           orow = (size_t)r;
            #pragma unroll
            for (int nt = 0; nt < 6; nt++) {
                float v0 = acc[mt][nt][half * 2 + 0] + bb[nt][0];
                float v1 = acc[mt][nt][half * 2 + 1] + bb[nt][1];
                if (MODE == 2) {
                    v0 = 0.5f * v0 * (1.0f + erff(v0 * 0.70710678118654752f));
                    v1 = 0.5f * v1 * (1.0f + erff(v1 * 0.70710678118654752f));
                    uint2* op2 = outp + orow * (size_t)(N >> 1) + ((n0 + wn) >> 1) + tig;
                    op2[nt * 4] = split_bf16_pair(v0, v1);
                } else {
                    float* op = out + orow * N + n0 + wn + tig * 2 + nt * 8;
                    if (MODE == 1 || MODE == 3) {
                        const float* rp = res + orow * N + n0 + wn + tig * 2 + nt * 8;
                        v0 += rp[0];
                        v1 += rp[1];
                    }
                    *(float2*)op = make_float2(v0, v1);
                }
            }
        }
    }
}

// ---------------- windowed attention (writes split pairs) ----------------
__global__ __launch_bounds__(192)
void attn_kernel(const float* __restrict__ qkv, const float* __restrict__ rpb) {
    __shared__ float ks[NHC][NNC * HEADC];
    __shared__ float vs[NHC][NNC * HEADC];
    __shared__ float btab[169 * NHC];
    __shared__ int   regn[NNC];

    int bw   = blockIdx.x;
    int base = bw * NNC;
    int tid  = threadIdx.x;

    for (int idx = tid; idx < NHC * NNC * HEADC; idx += 192) {
        int h = idx / (NNC * HEADC);
        int r = idx % (NNC * HEADC);
        int m = r >> 5, d = r & 31;
        const float* p = qkv + (size_t)(base + m) * (3 * DIMC);
        ks[h][r] = p[DIMC     + h * HEADC + d];
        vs[h][r] = p[2 * DIMC + h * HEADC + d];
    }
    for (int i = tid; i < 169 * NHC; i += 192) btab[i] = rpb[i];
    for (int i = tid; i < NNC; i += 192) {
        if (i < PC) { regn[i] = -1; }
        else {
            int p = i - PC;
            int r = p / 7, c = p % 7;
            int w = bw & 63;
            int gh = (w >> 3) * 7 + r;
            int gw = (w & 7) * 7 + c;
            int rh = gh < 49 ? 0 : (gh < 53 ? 1 : 2);
            int rw = gw < 49 ? 0 : (gw < 53 ? 1 : 2);
            regn[i] = rh * 3 + rw;
        }
    }
    __syncthreads();

    int head = tid / 64;
    int t    = tid % 64;
    if (t >= NNC) return;

    const float4* qp = (const float4*)(qkv + (size_t)(base + t) * (3 * DIMC) + head * HEADC);
    float4 q4[8];
    #pragma unroll
    for (int j = 0; j < 8; j++) {
        q4[j] = qp[j];
        q4[j].x *= SCALEC; q4[j].y *= SCALEC; q4[j].z *= SCALEC; q4[j].w *= SCALEC;
    }

    bool feat = (t >= PC);
    int rt = 0, ct = 0, myreg = -1;
    if (feat) { rt = (t - PC) / 7; ct = (t - PC) % 7; myreg = regn[t]; }

    const float* kh = ks[head];
    float s[NNC];
    #pragma unroll
    for (int m = 0; m < NNC; m++) {
        const float4* k4 = (const float4*)(kh + m * HEADC);
        float a = 0.f;
        #pragma unroll
        for (int j = 0; j < 8; j++) {
            float4 kk = k4[j];
            a += q4[j].x * kk.x + q4[j].y * kk.y + q4[j].z * kk.z + q4[j].w * kk.w;
        }
        float badd = 0.f;
        if (feat && m >= PC) {
            const int rm = (m - PC) / 7, cm = (m - PC) % 7;
            int idx = (rt - rm + 6) * 13 + (ct - cm + 6);
            badd = btab[idx * NHC + head];
            if (regn[m] != myreg) badd -= 100.f;
        }
        s[m] = a + badd;
    }

    float mx = s[0];
    #pragma unroll
    for (int m = 1; m < NNC; m++) mx = fmaxf(mx, s[m]);
    float sum = 0.f;
    #pragma unroll
    for (int m = 0; m < NNC; m++) { s[m] = __expf(s[m] - mx); sum += s[m]; }
    float inv = 1.0f / sum;

    float acc[HEADC];
    #pragma unroll
    for (int d = 0; d < HEADC; d++) acc[d] = 0.f;
    const float* vh = vs[head];
    #pragma unroll
    for (int m = 0; m < NNC; m++) {
        float pm = s[m] * inv;
        const float4* v4 = (const float4*)(vh + m * HEADC);
        #pragma unroll
        for (int j = 0; j < 8; j++) {
            float4 vv = v4[j];
            acc[4 * j + 0] += pm * vv.x;
            acc[4 * j + 1] += pm * vv.y;
            acc[4 * j + 2] += pm * vv.z;
            acc[4 * j + 3] += pm * vv.w;
        }
    }

    uint2* op = g_attno_sp + (size_t)(base + t) * 48 + head * 16;
    #pragma unroll
    for (int j = 0; j < 16; j++)
        op[j] = split_bf16_pair(acc[2 * j], acc[2 * j + 1]);
}

// ---------------- launch ----------------
extern "C" void kernel_launch(void* const* d_in, const int* in_sizes, int n_in,
                              void* d_out, int out_size) {
    const float* x       = (const float*)d_in[0];
    const float* norm1_g = (const float*)d_in[1];
    const float* norm1_b = (const float*)d_in[2];
    const float* qkv_w   = (const float*)d_in[3];
    const float* qkv_b   = (const float*)d_in[4];
    const float* rpb     = (const float*)d_in[5];
    const float* proj_w  = (const float*)d_in[6];
    const float* proj_b  = (const float*)d_in[7];
    const float* norm2_g = (const float*)d_in[8];
    const float* norm2_b = (const float*)d_in[9];
    const float* fc1_w   = (const float*)d_in[10];
    const float* fc1_b   = (const float*)d_in[11];
    const float* fc2_w   = (const float*)d_in[12];
    const float* fc2_b   = (const float*)d_in[13];
    float* out = (float*)d_out;

    uint2 *p_xw, *p_attno, *p_yn, *p_h, *p_wq, *p_wp, *p_w1, *p_w2;
    float *p_qkv, *p_y;
    cudaGetSymbolAddress((void**)&p_xw,    g_xw_sp);
    cudaGetSymbolAddress((void**)&p_qkv,   g_qkv);
    cudaGetSymbolAddress((void**)&p_attno, g_attno_sp);
    cudaGetSymbolAddress((void**)&p_y,     g_y);
    cudaGetSymbolAddress((void**)&p_yn,    g_yn_sp);
    cudaGetSymbolAddress((void**)&p_h,     g_h_sp);
    cudaGetSymbolAddress((void**)&p_wq,    g_wq_sp);
    cudaGetSymbolAddress((void**)&p_wp,    g_wp_sp);
    cudaGetSymbolAddress((void**)&p_w1,    g_w1_sp);
    cudaGetSymbolAddress((void**)&p_w2,    g_w2_sp);

    cudaFuncSetAttribute(gemm_tc<0>, cudaFuncAttributeMaxDynamicSharedMemorySize, GEMM_SMEM);
    cudaFuncSetAttribute(gemm_tc<1>, cudaFuncAttributeMaxDynamicSharedMemorySize, GEMM_SMEM);
    cudaFuncSetAttribute(gemm_tc<2>, cudaFuncAttributeMaxDynamicSharedMemorySize, GEMM_SMEM);
    cudaFuncSetAttribute(gemm_tc<3>, cudaFuncAttributeMaxDynamicSharedMemorySize, GEMM_SMEM);

    const int lnBlocks = (MROWS * 32 + 255) / 256;
    const int MB = MROWS / 128;   // 1728

    // 0. pre-split weights
    split_w_kernel<<<216, 256>>>(qkv_w, proj_w, fc1_w, fc2_w);
    // 1. LN1 + window gather (split out)
    ln_gather_kernel<<<lnBlocks, 256>>>(x, norm1_g, norm1_b);
    // 2. QKV GEMM  (N=288, K=96) -> float
    gemm_tc<0><<<dim3(3, MB), 256, GEMM_SMEM>>>(p_xw, p_wq, qkv_b, nullptr, p_qkv, nullptr, 288, 96);
    // 3. windowed attention (split out)
    attn_kernel<<<BATCHC * NWC, 192>>>(p_qkv, rpb);
    // 4. proj GEMM + scatter + residual-1  (N=96, K=96) -> float y
    gemm_tc<1><<<dim3(1, MB), 256, GEMM_SMEM>>>(p_attno, p_wp, proj_b, x, p_y, nullptr, 96, 96);
    // 5. LN2 (split out)
    ln_plain_kernel<<<lnBlocks, 256>>>(p_y, norm2_g, norm2_b);
    // 6. fc1 + GELU  (N=384, K=96) -> split h
    gemm_tc<2><<<dim3(4, MB), 256, GEMM_SMEM>>>(p_yn, p_w1, fc1_b, nullptr, nullptr, p_h, 384, 96);
    // 7. fc2 + residual-2 -> d_out  (N=96, K=384)
    gemm_tc<3><<<dim3(1, MB), 256, GEMM_SMEM>>>(p_h, p_w2, fc2_b, p_y, out, nullptr, 96, 384);
}

// round 5
// speedup vs baseline: 1.5348x; 1.0363x over previous
#include <cuda_runtime.h>
#include <cuda_bf16.h>
#include <math.h>

// ---------------- problem constants ----------------
#define DIMC    96
#define NHC     3
#define HEADC   32
#define WSC     7
#define SHIFTC  3
#define PC      5
#define HC      56
#define NWC     64
#define TPC     320
#define NNC     54
#define BATCHC  64
#define TOKC    3456
#define MROWS   (BATCHC * NWC * NNC)   // 221184
#define HIDC    384
#define SCALEC  0.17677669529663687f

// ---------------- scratch (split format: uint2{hi bf16 pair, lo bf16 pair}) ----------------
__device__ __align__(16) uint2 g_xw_sp   [MROWS * 48];            // LN1 out, window order
__device__ float               g_qkv     [(size_t)MROWS * 3 * DIMC];
__device__ __align__(16) uint2 g_attno_sp[MROWS * 48];            // attn out, window order
__device__ float               g_y       [MROWS * DIMC];          // residual stream (fp32)
__device__ __align__(16) uint2 g_yn_sp   [MROWS * 48];            // LN2 out
__device__ __align__(16) uint2 g_h_sp    [(size_t)MROWS * 192];   // fc1+GELU out
// pre-split weights [kpair][n]
__device__ __align__(16) uint2 g_wq_sp[48 * 288];
__device__ __align__(16) uint2 g_wp_sp[48 * 96];
__device__ __align__(16) uint2 g_w1_sp[48 * 384];
__device__ __align__(16) uint2 g_w2_sp[192 * 96];

__device__ __forceinline__ int map_token(int bw, int n) {
    int b = bw >> 6;
    int w = bw & 63;
    int tok;
    if (n < PC) {
        tok = w * PC + n;
    } else {
        int p  = n - PC;
        int r  = p / 7, c = p % 7;
        int wh = w >> 3, ww = w & 7;
        int hr = wh * 7 + r + SHIFTC; if (hr >= HC) hr -= HC;
        int wc = ww * 7 + c + SHIFTC; if (wc >= HC) wc -= HC;
        tok = TPC + hr * HC + wc;
    }
    return b * TOKC + tok;
}

__device__ __forceinline__ float warp_sum(float v) {
    #pragma unroll
    for (int o = 16; o; o >>= 1) v += __shfl_xor_sync(0xffffffffu, v, o);
    return v;
}

__device__ __forceinline__ uint2 split_bf16_pair(float x0, float x1) {
    __nv_bfloat16 h0 = __float2bfloat16(x0);
    __nv_bfloat16 h1 = __float2bfloat16(x1);
    float r0 = x0 - __bfloat162float(h0);
    float r1 = x1 - __bfloat162float(h1);
    __nv_bfloat16 l0 = __float2bfloat16(r0);
    __nv_bfloat16 l1 = __float2bfloat16(r1);
    uint2 o;
    o.x = ((unsigned)__bfloat16_as_ushort(h1) << 16) | (unsigned)__bfloat16_as_ushort(h0);
    o.y = ((unsigned)__bfloat16_as_ushort(l1) << 16) | (unsigned)__bfloat16_as_ushort(l0);
    return o;
}

// ---------------- weight pre-split ----------------
__global__ __launch_bounds__(256)
void split_w_kernel(const float* __restrict__ qkv_w, const float* __restrict__ proj_w,
                    const float* __restrict__ fc1_w, const float* __restrict__ fc2_w) {
    int i = blockIdx.x * blockDim.x + threadIdx.x;
    if (i < 13824) {
        int kp = i / 288, n = i % 288;
        g_wq_sp[i] = split_bf16_pair(qkv_w[(2 * kp) * 288 + n], qkv_w[(2 * kp + 1) * 288 + n]);
    } else if (i < 18432) {
        int j = i - 13824, kp = j / 96, n = j % 96;
        g_wp_sp[j] = split_bf16_pair(proj_w[(2 * kp) * 96 + n], proj_w[(2 * kp + 1) * 96 + n]);
    } else if (i < 36864) {
        int j = i - 18432, kp = j / 384, n = j % 384;
        g_w1_sp[j] = split_bf16_pair(fc1_w[(2 * kp) * 384 + n], fc1_w[(2 * kp + 1) * 384 + n]);
    } else if (i < 55296) {
        int j = i - 36864, kp = j / 96, n = j % 96;
        g_w2_sp[j] = split_bf16_pair(fc2_w[(2 * kp) * 96 + n], fc2_w[(2 * kp + 1) * 96 + n]);
    }
}

// ---------------- LN kernels (write split pairs) ----------------
__global__ __launch_bounds__(256)
void ln_gather_kernel(const float* __restrict__ x,
                      const float* __restrict__ g, const float* __restrict__ bta) {
    int row  = (blockIdx.x * blockDim.x + threadIdx.x) >> 5;
    int lane = threadIdx.x & 31;
    if (row >= MROWS) return;
    int bw = row / NNC, n = row % NNC;
    const float2* src2 = (const float2*)(x + (size_t)map_token(bw, n) * DIMC);
    float2 a0 = src2[lane];
    float2 a1 = make_float2(0.f, 0.f);
    if (lane < 16) a1 = src2[32 + lane];
    float s = a0.x + a0.y + a1.x + a1.y;
    float mean = warp_sum(s) * (1.f / 96.f);
    float d0x = a0.x - mean, d0y = a0.y - mean;
    float d1x = a1.x - mean, d1y = a1.y - mean;
    float vq = d0x * d0x + d0y * d0y + (lane < 16 ? d1x * d1x + d1y * d1y : 0.f);
    float var = warp_sum(vq) * (1.f / 96.f);
    float inv = rsqrtf(var + 1e-5f);
    const float2* g2 = (const float2*)g;
    const float2* b2 = (const float2*)bta;
    uint2* dst = g_xw_sp + (size_t)row * 48;
    float2 G = g2[lane], B = b2[lane];
    dst[lane] = split_bf16_pair(d0x * inv * G.x + B.x, d0y * inv * G.y + B.y);
    if (lane < 16) {
        float2 G1 = g2[32 + lane], B1 = b2[32 + lane];
        dst[32 + lane] = split_bf16_pair(d1x * inv * G1.x + B1.x, d1y * inv * G1.y + B1.y);
    }
}

__global__ __launch_bounds__(256)
void ln_plain_kernel(const float* __restrict__ y,
                     const float* __restrict__ g, const float* __restrict__ bta) {
    int row  = (blockIdx.x * blockDim.x + threadIdx.x) >> 5;
    int lane = threadIdx.x & 31;
    if (row >= MROWS) return;
    const float2* src2 = (const float2*)(y + (size_t)row * DIMC);
    float2 a0 = src2[lane];
    float2 a1 = make_float2(0.f, 0.f);
    if (lane < 16) a1 = src2[32 + lane];
    float s = a0.x + a0.y + a1.x + a1.y;
    float mean = warp_sum(s) * (1.f / 96.f);
    float d0x = a0.x - mean, d0y = a0.y - mean;
    float d1x = a1.x - mean, d1y = a1.y - mean;
    float vq = d0x * d0x + d0y * d0y + (lane < 16 ? d1x * d1x + d1y * d1y : 0.f);
    float var = warp_sum(vq) * (1.f / 96.f);
    float inv = rsqrtf(var + 1e-5f);
    const float2* g2 = (const float2*)g;
    const float2* b2 = (const float2*)bta;
    uint2* dst = g_yn_sp + (size_t)row * 48;
    float2 G = g2[lane], B = b2[lane];
    dst[lane] = split_bf16_pair(d0x * inv * G.x + B.x, d0y * inv * G.y + B.y);
    if (lane < 16) {
        float2 G1 = g2[32 + lane], B1 = b2[32 + lane];
        dst[32 + lane] = split_bf16_pair(d1x * inv * G1.x + B1.x, d1y * inv * G1.y + B1.y);
    }
}

// ---------------- BF16x3 tensor-core GEMM (unchanged from R4) ----------------
__device__ __forceinline__ void mma16(float c[4],
                                      unsigned a0, unsigned a1, unsigned a2, unsigned a3,
                                      unsigned b0, unsigned b1) {
    asm volatile("mma.sync.aligned.m16n8k16.row.col.f32.bf16.bf16.f32 "
                 "{%0,%1,%2,%3}, {%4,%5,%6,%7}, {%8,%9}, {%0,%1,%2,%3};\n"
                 : "+f"(c[0]), "+f"(c[1]), "+f"(c[2]), "+f"(c[3])
                 : "r"(a0), "r"(a1), "r"(a2), "r"(a3), "r"(b0), "r"(b1));
}

#define GEMM_SMEM ((2 * 16 * 132 + 2 * 16 * 100) * 8)   // 59392 bytes

template<int MODE>
__global__ __launch_bounds__(256, 2)
void gemm_tc(const uint2* __restrict__ A, const uint2* __restrict__ Bw,
             const float* __restrict__ bias, const float* __restrict__ res,
             float* __restrict__ out, uint2* __restrict__ outp, int N, int K) {
    extern __shared__ uint2 smemu[];
    uint2 (*As2)[16][132] = reinterpret_cast<uint2(*)[16][132]>(smemu);
    uint2 (*Bs2)[16][100] = reinterpret_cast<uint2(*)[16][100]>(smemu + 2 * 16 * 132);

    const int tid  = threadIdx.x;
    const int wid  = tid >> 5, lane = tid & 31;
    const int gid  = lane >> 2, tig = lane & 3;
    const int wm   = (wid >> 1) * 32;
    const int wn   = (wid & 1) * 48;
    const int m0   = blockIdx.y * 128;
    const int n0   = blockIdx.x * 96;
    const int KP   = K >> 1;

    int arow[4], akp[4];
    const uint2* aPtr[4];
    #pragma unroll
    for (int j = 0; j < 4; j++) {
        int c = tid + 256 * j;
        arow[j] = c >> 3;
        akp[j]  = (c & 7) * 2;
        aPtr[j] = A + (size_t)(m0 + arow[j]) * KP + akp[j];
    }
    int bkp[3], bn2[3];
    const uint2* bPtr[3];
    #pragma unroll
    for (int j = 0; j < 3; j++) {
        int c = tid + 256 * j;
        bkp[j] = c / 48;
        bn2[j] = (c % 48) * 2;
        bPtr[j] = Bw + (size_t)bkp[j] * N + n0 + bn2[j];
    }

    float acc[2][6][4];
    #pragma unroll
    for (int i = 0; i < 2; i++)
        #pragma unroll
        for (int j = 0; j < 6; j++)
            #pragma unroll
            for (int r = 0; r < 4; r++) acc[i][j][r] = 0.f;

    uint4 aR[4], bR[3];
    #pragma unroll
    for (int j = 0; j < 4; j++) aR[j] = *(const uint4*)(aPtr[j]);
    #pragma unroll
    for (int j = 0; j < 3; j++) bR[j] = *(const uint4*)(bPtr[j]);

    #pragma unroll
    for (int j = 0; j < 4; j++) {
        As2[0][akp[j]][arow[j]]     = make_uint2(aR[j].x, aR[j].y);
        As2[0][akp[j] + 1][arow[j]] = make_uint2(aR[j].z, aR[j].w);
    }
    #pragma unroll
    for (int j = 0; j < 3; j++)
        *(uint4*)&Bs2[0][bkp[j]][bn2[j]] = bR[j];
    __syncthreads();

    const int T = K >> 5;
    for (int t = 0; t < T; t++) {
        const int s = t & 1;
        if (t + 1 < T) {
            const int kt = 16 * (t + 1);
            #pragma unroll
            for (int j = 0; j < 4; j++) aR[j] = *(const uint4*)(aPtr[j] + kt);
            #pragma unroll
            for (int j = 0; j < 3; j++) bR[j] = *(const uint4*)(bPtr[j] + (size_t)kt * N);
        }

        #pragma unroll
        for (int ks = 0; ks < 2; ks++) {
            const int kb = ks * 8;
            uint2 af[2][4];
            #pragma unroll
            for (int mt = 0; mt < 2; mt++) {
                const int m = wm + mt * 16 + gid;
                af[mt][0] = As2[s][kb + tig    ][m];
                af[mt][1] = As2[s][kb + tig    ][m + 8];
                af[mt][2] = As2[s][kb + tig + 4][m];
                af[mt][3] = As2[s][kb + tig + 4][m + 8];
            }
            uint2 bf[6][2];
            #pragma unroll
            for (int nt = 0; nt < 6; nt++) {
                const int n = wn + nt * 8 + gid;
                bf[nt][0] = Bs2[s][kb + tig    ][n];
                bf[nt][1] = Bs2[s][kb + tig + 4][n];
            }
            #pragma unroll
            for (int mt = 0; mt < 2; mt++)
                #pragma unroll
                for (int nt = 0; nt < 6; nt++) {
                    float* c = acc[mt][nt];
                    mma16(c, af[mt][0].x, af[mt][1].x, af[mt][2].x, af[mt][3].x,
                             bf[nt][0].x, bf[nt][1].x);
                    mma16(c, af[mt][0].x, af[mt][1].x, af[mt][2].x, af[mt][3].x,
                             bf[nt][0].y, bf[nt][1].y);
                    mma16(c, af[mt][0].y, af[mt][1].y, af[mt][2].y, af[mt][3].y,
                             bf[nt][0].x, bf[nt][1].x);
                }
        }

        if (t + 1 < T) {
            const int sn = (t + 1) & 1;
            #pragma unroll
            for (int j = 0; j < 4; j++) {
                As2[sn][akp[j]][arow[j]]     = make_uint2(aR[j].x, aR[j].y);
                As2[sn][akp[j] + 1][arow[j]] = make_uint2(aR[j].z, aR[j].w);
            }
            #pragma unroll
            for (int j = 0; j < 3; j++)
                *(uint4*)&Bs2[sn][bkp[j]][bn2[j]] = bR[j];
        }
        __syncthreads();
    }

    float bb[6][2];
    #pragma unroll
    for (int nt = 0; nt < 6; nt++) {
        int c = n0 + wn + nt * 8 + tig * 2;
        bb[nt][0] = bias[c];
        bb[nt][1] = bias[c + 1];
    }

    #pragma unroll
    for (int mt = 0; mt < 2; mt++) {
        #pragma unroll
        for (int half = 0; half < 2; half++) {
            int r = m0 + wm + mt * 16 + gid + half * 8;
            size_t orow;
            if (MODE == 1) orow = (size_t)map_token(r / NNC, r % NNC);
            else           orow = (size_t)r;
            #pragma unroll
            for (int nt = 0; nt < 6; nt++) {
                float v0 = acc[mt][nt][half * 2 + 0] + bb[nt][0];
                float v1 = acc[mt][nt][half * 2 + 1] + bb[nt][1];
                if (MODE == 2) {
                    v0 = 0.5f * v0 * (1.0f + erff(v0 * 0.70710678118654752f));
                    v1 = 0.5f * v1 * (1.0f + erff(v1 * 0.70710678118654752f));
                    uint2* op2 = outp + orow * (size_t)(N >> 1) + ((n0 + wn) >> 1) + tig;
                    op2[nt * 4] = split_bf16_pair(v0, v1);
                } else {
                    float* op = out + orow * N + n0 + wn + tig * 2 + nt * 8;
                    if (MODE == 1 || MODE == 3) {
                        const float* rp = res + orow * N + n0 + wn + tig * 2 + nt * 8;
                        v0 += rp[0];
                        v1 += rp[1];
                    }
                    *(float2*)op = make_float2(v0, v1);
                }
            }
        }
    }
}

// ---------------- windowed attention: one block per (window, head) ----------------
// 64 threads; 8 CTAs/SM forced (regs <= 128). K/V for this head staged in smem,
// bias/mask folded into ~4 inner ops via fidx table + per-thread bitmask.
__global__ __launch_bounds__(64, 8)
void attn_kernel(const float* __restrict__ qkv, const float* __restrict__ rpb) {
    __shared__ float ks[NNC * HEADC];       // 6912 B
    __shared__ float vs[NNC * HEADC];       // 6912 B
    __shared__ float bt[169];
    __shared__ unsigned char fidx_s[49];    // rm*13+cm per feature key
    __shared__ int regn_s[NNC];

    const int bw   = blockIdx.x;            // window id
    const int head = blockIdx.y;
    const int base = bw * NNC;
    const int tid  = threadIdx.x;

    // stage K/V for this head (each warp reads 32 contiguous floats)
    for (int idx = tid; idx < NNC * HEADC; idx += 64) {
        int m = idx >> 5, d = idx & 31;
        const float* p = qkv + (size_t)(base + m) * (3 * DIMC) + head * HEADC + d;
        ks[idx] = p[DIMC];
        vs[idx] = p[2 * DIMC];
    }
    for (int i = tid; i < 169; i += 64) bt[i] = rpb[i * NHC + head];
    if (tid < 49) fidx_s[tid] = (unsigned char)((tid / 7) * 13 + (tid % 7));
    if (tid < NNC) {
        int i = tid;
        if (i < PC) regn_s[i] = -1;
        else {
            int p = i - PC;
            int r = p / 7, c = p % 7;
            int w = bw & 63;
            int gh = (w >> 3) * 7 + r;
            int gw = (w & 7) * 7 + c;
            int rh = gh < 49 ? 0 : (gh < 53 ? 1 : 2);
            int rw = gw < 49 ? 0 : (gw < 53 ? 1 : 2);
            regn_s[i] = rh * 3 + rw;
        }
    }
    __syncthreads();

    const int t = tid;
    if (t >= NNC) return;

    // Q row (scaled) in registers
    const float4* qp = (const float4*)(qkv + (size_t)(base + t) * (3 * DIMC) + head * HEADC);
    float4 q4[8];
    #pragma unroll
    for (int j = 0; j < 8; j++) {
        q4[j] = qp[j];
        q4[j].x *= SCALEC; q4[j].y *= SCALEC; q4[j].z *= SCALEC; q4[j].w *= SCALEC;
    }

    const bool feat = (t >= PC);
    int tb = 0;
    unsigned mlo = 0, mhi = 0;                // per-thread mask bitmask over m
    if (feat) {
        int p = t - PC;
        tb = (p / 7 + 6) * 13 + (p % 7 + 6);
        int myreg = regn_s[t];
        #pragma unroll 7
        for (int m = PC; m < NNC; m++) {
            if (regn_s[m] != myreg) {
                if (m < 32) mlo |= 1u << m;
                else        mhi |= 1u << (m - 32);
            }
        }
    }

    // ---- scores ----
    float s[NNC];
    #pragma unroll 6
    for (int m = 0; m < NNC; m++) {
        const float4* k4 = (const float4*)(ks + m * HEADC);
        float4 k0 = k4[0], k1 = k4[1], k2 = k4[2], k3 = k4[3];
        float4 k5 = k4[4], k6 = k4[5], k7 = k4[6], k8 = k4[7];
        float a0 = q4[0].x * k0.x + q4[0].y * k0.y + q4[0].z * k0.z + q4[0].w * k0.w;
        float a1 = q4[1].x * k1.x + q4[1].y * k1.y + q4[1].z * k1.z + q4[1].w * k1.w;
        float a2 = q4[2].x * k2.x + q4[2].y * k2.y + q4[2].z * k2.z + q4[2].w * k2.w;
        float a3 = q4[3].x * k3.x + q4[3].y * k3.y + q4[3].z * k3.z + q4[3].w * k3.w;
        a0 += q4[4].x * k5.x + q4[4].y * k5.y + q4[4].z * k5.z + q4[4].w * k5.w;
        a1 += q4[5].x * k6.x + q4[5].y * k6.y + q4[5].z * k6.z + q4[5].w * k6.w;
        a2 += q4[6].x * k7.x + q4[6].y * k7.y + q4[6].z * k7.z + q4[6].w * k7.w;
        a3 += q4[7].x * k8.x + q4[7].y * k8.y + q4[7].z * k8.z + q4[7].w * k8.w;
        float a = (a0 + a1) + (a2 + a3);
        if (feat && m >= PC) {
            int idx = tb - (int)fidx_s[m - PC];
            float badd = bt[idx];
            bool msk = (m < 32) ? ((mlo >> m) & 1u) : ((mhi >> (m - 32)) & 1u);
            a += msk ? (badd - 100.f) : badd;
        }
        s[m] = a;
    }

    // ---- softmax ----
    float mx = s[0];
    #pragma unroll
    for (int m = 1; m < NNC; m++) mx = fmaxf(mx, s[m]);
    float sum = 0.f;
    #pragma unroll
    for (int m = 0; m < NNC; m++) { s[m] = __expf(s[m] - mx); sum += s[m]; }
    const float inv = 1.0f / sum;

    // ---- P @ V ----
    float acc[HEADC];
    #pragma unroll
    for (int d = 0; d < HEADC; d++) acc[d] = 0.f;
    #pragma unroll 6
    for (int m = 0; m < NNC; m++) {
        const float pm = s[m] * inv;
        const float4* v4 = (const float4*)(vs + m * HEADC);
        #pragma unroll
        for (int j = 0; j < 8; j++) {
            float4 vv = v4[j];
            acc[4 * j + 0] += pm * vv.x;
            acc[4 * j + 1] += pm * vv.y;
            acc[4 * j + 2] += pm * vv.z;
            acc[4 * j + 3] += pm * vv.w;
        }
    }

    // write split pairs for the proj GEMM
    uint2* op = g_attno_sp + (size_t)(base + t) * 48 + head * 16;
    #pragma unroll
    for (int j = 0; j < 16; j++)
        op[j] = split_bf16_pair(acc[2 * j], acc[2 * j + 1]);
}

// ---------------- launch ----------------
extern "C" void kernel_launch(void* const* d_in, const int* in_sizes, int n_in,
                              void* d_out, int out_size) {
    const float* x       = (const float*)d_in[0];
    const float* norm1_g = (const float*)d_in[1];
    const float* norm1_b = (const float*)d_in[2];
    const float* qkv_w   = (const float*)d_in[3];
    const float* qkv_b   = (const float*)d_in[4];
    const float* rpb     = (const float*)d_in[5];
    const float* proj_w  = (const float*)d_in[6];
    const float* proj_b  = (const float*)d_in[7];
    const float* norm2_g = (const float*)d_in[8];
    const float* norm2_b = (const float*)d_in[9];
    const float* fc1_w   = (const float*)d_in[10];
    const float* fc1_b   = (const float*)d_in[11];
    const float* fc2_w   = (const float*)d_in[12];
    const float* fc2_b   = (const float*)d_in[13];
    float* out = (float*)d_out;

    uint2 *p_xw, *p_attno, *p_yn, *p_h, *p_wq, *p_wp, *p_w1, *p_w2;
    float *p_qkv, *p_y;
    cudaGetSymbolAddress((void**)&p_xw,    g_xw_sp);
    cudaGetSymbolAddress((void**)&p_qkv,   g_qkv);
    cudaGetSymbolAddress((void**)&p_attno, g_attno_sp);
    cudaGetSymbolAddress((void**)&p_y,     g_y);
    cudaGetSymbolAddress((void**)&p_yn,    g_yn_sp);
    cudaGetSymbolAddress((void**)&p_h,     g_h_sp);
    cudaGetSymbolAddress((void**)&p_wq,    g_wq_sp);
    cudaGetSymbolAddress((void**)&p_wp,    g_wp_sp);
    cudaGetSymbolAddress((void**)&p_w1,    g_w1_sp);
    cudaGetSymbolAddress((void**)&p_w2,    g_w2_sp);

    cudaFuncSetAttribute(gemm_tc<0>, cudaFuncAttributeMaxDynamicSharedMemorySize, GEMM_SMEM);
    cudaFuncSetAttribute(gemm_tc<1>, cudaFuncAttributeMaxDynamicSharedMemorySize, GEMM_SMEM);
    cudaFuncSetAttribute(gemm_tc<2>, cudaFuncAttributeMaxDynamicSharedMemorySize, GEMM_SMEM);
    cudaFuncSetAttribute(gemm_tc<3>, cudaFuncAttributeMaxDynamicSharedMemorySize, GEMM_SMEM);

    const int lnBlocks = (MROWS * 32 + 255) / 256;
    const int MB = MROWS / 128;   // 1728

    // 0. pre-split weights
    split_w_kernel<<<216, 256>>>(qkv_w, proj_w, fc1_w, fc2_w);
    // 1. LN1 + window gather (split out)
    ln_gather_kernel<<<lnBlocks, 256>>>(x, norm1_g, norm1_b);
    // 2. QKV GEMM  (N=288, K=96) -> float
    gemm_tc<0><<<dim3(3, MB), 256, GEMM_SMEM>>>(p_xw, p_wq, qkv_b, nullptr, p_qkv, nullptr, 288, 96);
    // 3. windowed attention (split out), one block per (window, head)
    attn_kernel<<<dim3(BATCHC * NWC, NHC), 64>>>(p_qkv, rpb);
    // 4. proj GEMM + scatter + residual-1  (N=96, K=96) -> float y
    gemm_tc<1><<<dim3(1, MB), 256, GEMM_SMEM>>>(p_attno, p_wp, proj_b, x, p_y, nullptr, 96, 96);
    // 5. LN2 (split out)
    ln_plain_kernel<<<lnBlocks, 256>>>(p_y, norm2_g, norm2_b);
    // 6. fc1 + GELU  (N=384, K=96) -> split h
    gemm_tc<2><<<dim3(4, MB), 256, GEMM_SMEM>>>(p_yn, p_w1, fc1_b, nullptr, nullptr, p_h, 384, 96);
    // 7. fc2 + residual-2 -> d_out  (N=96, K=384)
    gemm_tc<3><<<dim3(1, MB), 256, GEMM_SMEM>>>(p_h, p_w2, fc2_b, p_y, out, nullptr, 96, 384);
}